// round 1
// baseline (speedup 1.0000x reference)
#include <cuda_runtime.h>
#include <cuda_bf16.h>
#include <math.h>

// Problem constants
#define BB   2
#define NN   2048
#define CC   512
#define HEADS 8
#define DH   64
#define WIN  64
#define RR   8
#define MTOT (BB*NN)        // 4096
#define QKVC (3*CC)         // 1536
#define LORA_SC 0.25f

// Scratch (device globals; no allocation allowed)
__device__ float g_weff[CC*QKVC];     // 512*1536
__device__ float g_wout[CC*CC];       // 512*512
__device__ float g_qkv[MTOT*QKVC];    // 4096*1536
__device__ float g_att[MTOT*CC];      // 4096*512

// ---------------------------------------------------------------------------
// Fold LoRA into effective weight: out[i][j] = W[i][j] + 0.25 * sum_r A[i][r]*B[r][j]
// ---------------------------------------------------------------------------
__global__ void fuse_w_kernel(const float* __restrict__ W,
                              const float* __restrict__ A,
                              const float* __restrict__ Bm,
                              float* __restrict__ out, int Nn) {
    int idx = blockIdx.x * blockDim.x + threadIdx.x;
    int total = CC * Nn;
    if (idx >= total) return;
    int i = idx / Nn;
    int j = idx - i * Nn;
    float acc = W[idx];
    #pragma unroll
    for (int r = 0; r < RR; r++)
        acc += LORA_SC * A[i*RR + r] * Bm[r*Nn + j];
    out[idx] = acc;
}

// ---------------------------------------------------------------------------
// fp32 tiled GEMM: C[M][Nn] = A[M][K] * B[K][Nn] (+ bias)
// BM=BN=64, BK=16, 256 threads, 4x4 microtile per thread
// ---------------------------------------------------------------------------
#define BM 64
#define BN 64
#define BK 16
#define AS_STRIDE 68   // padded (float4-aligned, reduces store conflicts)

__global__ __launch_bounds__(256) void sgemm_kernel(
    const float* __restrict__ A, const float* __restrict__ B,
    const float* __restrict__ bias, float* __restrict__ C,
    int M, int Nn, int K) {
    __shared__ float As[BK * AS_STRIDE];   // transposed: As[k][m]
    __shared__ float Bs[BK * BN];          // Bs[k][n]

    int tid = threadIdx.x;
    int bm = blockIdx.y * BM;
    int bn = blockIdx.x * BN;

    int tr = (tid >> 4) * 4;    // row offset in tile (0..60)
    int tc = (tid & 15) * 4;    // col offset in tile (0..60)

    float acc[4][4];
    #pragma unroll
    for (int i = 0; i < 4; i++)
        #pragma unroll
        for (int j = 0; j < 4; j++) acc[i][j] = 0.f;

    // A-load indices: thread loads one float4 along K
    int ar = tid >> 2;            // 0..63 (row within tile)
    int ac = (tid & 3) * 4;       // 0..12 (k within tile)
    // B-load indices
    int br = tid >> 4;            // 0..15 (k within tile)
    int bc = (tid & 15) * 4;      // 0..60 (col within tile)

    for (int k0 = 0; k0 < K; k0 += BK) {
        float4 a4 = *(const float4*)&A[(size_t)(bm + ar) * K + k0 + ac];
        As[(ac+0)*AS_STRIDE + ar] = a4.x;
        As[(ac+1)*AS_STRIDE + ar] = a4.y;
        As[(ac+2)*AS_STRIDE + ar] = a4.z;
        As[(ac+3)*AS_STRIDE + ar] = a4.w;
        *(float4*)&Bs[br*BN + bc] = *(const float4*)&B[(size_t)(k0 + br) * Nn + bn + bc];
        __syncthreads();

        #pragma unroll
        for (int k = 0; k < BK; k++) {
            float4 av = *(const float4*)&As[k*AS_STRIDE + tr];
            float4 bv = *(const float4*)&Bs[k*BN + tc];
            float a[4] = {av.x, av.y, av.z, av.w};
            float b[4] = {bv.x, bv.y, bv.z, bv.w};
            #pragma unroll
            for (int i = 0; i < 4; i++)
                #pragma unroll
                for (int j = 0; j < 4; j++)
                    acc[i][j] += a[i] * b[j];
        }
        __syncthreads();
    }

    float4 bb = make_float4(0.f, 0.f, 0.f, 0.f);
    if (bias) bb = *(const float4*)&bias[bn + tc];
    #pragma unroll
    for (int i = 0; i < 4; i++) {
        float4 o = make_float4(acc[i][0] + bb.x, acc[i][1] + bb.y,
                               acc[i][2] + bb.z, acc[i][3] + bb.w);
        *(float4*)&C[(size_t)(bm + tr + i) * Nn + bn + tc] = o;
    }
}

// ---------------------------------------------------------------------------
// Attention: per block = (64-query tile, head, batch).
// Local causal window of 65 keys (within a 128-key contiguous span) + unmasked
// global attention over 32 strided keys (stride WINDOW). Outputs summed.
// ---------------------------------------------------------------------------
#define KSTR 68     // K/V/Q smem row stride (floats)
#define SSTR 133    // local score row stride
#define GSTR 37     // global score row stride

// smem layout sizes (floats)
#define OFF_Q   0
#define OFF_K   (OFF_Q  + 64*KSTR)
#define OFF_V   (OFF_K  + 128*KSTR)
#define OFF_KG  (OFF_V  + 128*KSTR)
#define OFF_VG  (OFF_KG + 32*KSTR)
#define OFF_S   (OFF_VG + 32*KSTR)
#define OFF_SG  (OFF_S  + 64*SSTR)
#define SMEM_FLOATS (OFF_SG + 64*GSTR)

__global__ __launch_bounds__(256) void attn_kernel(float* __restrict__ outp) {
    extern __shared__ float sm[];
    float* sQ  = sm + OFF_Q;
    float* sK  = sm + OFF_K;
    float* sV  = sm + OFF_V;
    float* sKg = sm + OFF_KG;
    float* sVg = sm + OFF_VG;
    float* sS  = sm + OFF_S;
    float* sSg = sm + OFF_SG;

    const float* qkv = g_qkv;
    int qb = blockIdx.x, h = blockIdx.y, b = blockIdx.z;
    int tid = threadIdx.x;
    int qstart = qb * 64;
    const float scale = 0.125f;   // dh^-0.5 = 1/8

    // ---- load tiles ----
    // Q: 64 rows x 16 float4
    for (int idx = tid; idx < 64*16; idx += 256) {
        int r = idx >> 4, c = idx & 15;
        size_t base = ((size_t)(b*NN + qstart + r)) * QKVC + h*DH + c*4;
        *(float4*)&sQ[r*KSTR + c*4] = *(const float4*)&qkv[base];
    }
    // K,V local: rows 0..127 -> key index qstart-64+r (clamped; masked later)
    for (int idx = tid; idx < 128*16; idx += 256) {
        int r = idx >> 4, c = idx & 15;
        int kidx = qstart - 64 + r; if (kidx < 0) kidx = 0;
        size_t base = ((size_t)(b*NN + kidx)) * QKVC + h*DH + c*4;
        *(float4*)&sK[r*KSTR + c*4] = *(const float4*)&qkv[base + CC];
        *(float4*)&sV[r*KSTR + c*4] = *(const float4*)&qkv[base + 2*CC];
    }
    // global K/V: keys j*WIN, j=0..31
    for (int idx = tid; idx < 32*16; idx += 256) {
        int r = idx >> 4, c = idx & 15;
        size_t base = ((size_t)(b*NN + r*WIN)) * QKVC + h*DH + c*4;
        *(float4*)&sKg[r*KSTR + c*4] = *(const float4*)&qkv[base + CC];
        *(float4*)&sVg[r*KSTR + c*4] = *(const float4*)&qkv[base + 2*CC];
    }
    __syncthreads();

    int qi = tid >> 2;          // 0..63 query within tile
    int lane4 = tid & 3;
    int gi = qstart + qi;       // global query index
    const float NEG = -1e30f;

    // ---- local scores: each thread 32 keys ----
    #pragma unroll 4
    for (int s = 0; s < 32; s++) {
        int r = lane4 + 4*s;
        float acc = 0.f;
        #pragma unroll
        for (int c = 0; c < 16; c++) {
            float4 a  = *(const float4*)&sQ[qi*KSTR + c*4];
            float4 kk = *(const float4*)&sK[r*KSTR + c*4];
            acc += a.x*kk.x + a.y*kk.y + a.z*kk.z + a.w*kk.w;
        }
        int kidx = qstart - 64 + r;
        bool valid = (kidx >= 0) && (kidx <= gi) && (gi - kidx <= WIN);
        sS[qi*SSTR + r] = valid ? acc * scale : NEG;
    }
    // ---- global scores: each thread 8 keys (no mask) ----
    #pragma unroll
    for (int s = 0; s < 8; s++) {
        int r = lane4 + 4*s;
        float acc = 0.f;
        #pragma unroll
        for (int c = 0; c < 16; c++) {
            float4 a  = *(const float4*)&sQ[qi*KSTR + c*4];
            float4 kk = *(const float4*)&sKg[r*KSTR + c*4];
            acc += a.x*kk.x + a.y*kk.y + a.z*kk.z + a.w*kk.w;
        }
        sSg[qi*GSTR + r] = acc * scale;
    }
    __syncthreads();

    // ---- softmax (one thread per query row) ----
    if (tid < 64) {
        int q = tid;
        float m = NEG;
        for (int r = 0; r < 128; r++) m = fmaxf(m, sS[q*SSTR + r]);
        float sum = 0.f;
        for (int r = 0; r < 128; r++) {
            float e = __expf(sS[q*SSTR + r] - m);
            sS[q*SSTR + r] = e; sum += e;
        }
        float inv = 1.f / sum;
        for (int r = 0; r < 128; r++) sS[q*SSTR + r] *= inv;

        float mg = NEG;
        for (int r = 0; r < 32; r++) mg = fmaxf(mg, sSg[q*GSTR + r]);
        float sg = 0.f;
        for (int r = 0; r < 32; r++) {
            float e = __expf(sSg[q*GSTR + r] - mg);
            sSg[q*GSTR + r] = e; sg += e;
        }
        float ig = 1.f / sg;
        for (int r = 0; r < 32; r++) sSg[q*GSTR + r] *= ig;
    }
    __syncthreads();

    // ---- P*V: thread computes 16 output dims for query qi ----
    int d0 = lane4 * 16;
    float4 o0 = make_float4(0,0,0,0), o1 = o0, o2 = o0, o3 = o0;
    for (int r = 0; r < 128; r++) {
        float p = sS[qi*SSTR + r];
        float4 v0 = *(const float4*)&sV[r*KSTR + d0 + 0];
        float4 v1 = *(const float4*)&sV[r*KSTR + d0 + 4];
        float4 v2 = *(const float4*)&sV[r*KSTR + d0 + 8];
        float4 v3 = *(const float4*)&sV[r*KSTR + d0 + 12];
        o0.x += p*v0.x; o0.y += p*v0.y; o0.z += p*v0.z; o0.w += p*v0.w;
        o1.x += p*v1.x; o1.y += p*v1.y; o1.z += p*v1.z; o1.w += p*v1.w;
        o2.x += p*v2.x; o2.y += p*v2.y; o2.z += p*v2.z; o2.w += p*v2.w;
        o3.x += p*v3.x; o3.y += p*v3.y; o3.z += p*v3.z; o3.w += p*v3.w;
    }
    for (int r = 0; r < 32; r++) {
        float p = sSg[qi*GSTR + r];
        float4 v0 = *(const float4*)&sVg[r*KSTR + d0 + 0];
        float4 v1 = *(const float4*)&sVg[r*KSTR + d0 + 4];
        float4 v2 = *(const float4*)&sVg[r*KSTR + d0 + 8];
        float4 v3 = *(const float4*)&sVg[r*KSTR + d0 + 12];
        o0.x += p*v0.x; o0.y += p*v0.y; o0.z += p*v0.z; o0.w += p*v0.w;
        o1.x += p*v1.x; o1.y += p*v1.y; o1.z += p*v1.z; o1.w += p*v1.w;
        o2.x += p*v2.x; o2.y += p*v2.y; o2.z += p*v2.z; o2.w += p*v2.w;
        o3.x += p*v3.x; o3.y += p*v3.y; o3.z += p*v3.z; o3.w += p*v3.w;
    }
    size_t ob = ((size_t)(b*NN + gi)) * CC + h*DH + d0;
    *(float4*)&outp[ob + 0]  = o0;
    *(float4*)&outp[ob + 4]  = o1;
    *(float4*)&outp[ob + 8]  = o2;
    *(float4*)&outp[ob + 12] = o3;
}

// ---------------------------------------------------------------------------
// launch
// ---------------------------------------------------------------------------
extern "C" void kernel_launch(void* const* d_in, const int* in_sizes, int n_in,
                              void* d_out, int out_size) {
    const float* x       = (const float*)d_in[0];
    const float* w_qkv   = (const float*)d_in[1];
    const float* lA_qkv  = (const float*)d_in[2];
    const float* lB_qkv  = (const float*)d_in[3];
    const float* w_out   = (const float*)d_in[4];
    const float* b_out   = (const float*)d_in[5];
    const float* lA_out  = (const float*)d_in[6];
    const float* lB_out  = (const float*)d_in[7];
    float* out = (float*)d_out;

    float *p_weff, *p_wout, *p_qkv, *p_att;
    cudaGetSymbolAddress((void**)&p_weff, g_weff);
    cudaGetSymbolAddress((void**)&p_wout, g_wout);
    cudaGetSymbolAddress((void**)&p_qkv,  g_qkv);
    cudaGetSymbolAddress((void**)&p_att,  g_att);

    // 1. fold LoRA into effective weights
    {
        int total = CC * QKVC;
        fuse_w_kernel<<<(total + 255)/256, 256>>>(w_qkv, lA_qkv, lB_qkv, p_weff, QKVC);
        total = CC * CC;
        fuse_w_kernel<<<(total + 255)/256, 256>>>(w_out, lA_out, lB_out, p_wout, CC);
    }
    // 2. qkv = x @ w_eff
    {
        dim3 grid(QKVC/BN, MTOT/BM);
        sgemm_kernel<<<grid, 256>>>(x, p_weff, nullptr, p_qkv, MTOT, QKVC, CC);
    }
    // 3. attention
    {
        static size_t smem_bytes = SMEM_FLOATS * sizeof(float);
        cudaFuncSetAttribute(attn_kernel, cudaFuncAttributeMaxDynamicSharedMemorySize,
                             (int)smem_bytes);
        dim3 grid(NN/64, HEADS, BB);
        attn_kernel<<<grid, 256, smem_bytes>>>(p_att);
    }
    // 4. out = att @ w_out_eff + b_out
    {
        dim3 grid(CC/BN, MTOT/BM);
        sgemm_kernel<<<grid, 256>>>(p_att, p_wout, b_out, out, MTOT, CC, CC);
    }
}

// round 2
// speedup vs baseline: 2.4910x; 2.4910x over previous
#include <cuda_runtime.h>
#include <cuda_bf16.h>
#include <math.h>
#include <stdint.h>

// Problem constants
#define BB   2
#define NN   2048
#define CC   512
#define HEADS 8
#define DH   64
#define WIN  64
#define RR   8
#define MTOT (BB*NN)        // 4096
#define QKVC (3*CC)         // 1536
#define LORA_SC 0.25f

// Scratch (device globals; no allocation allowed)
__device__ float g_weff[CC*QKVC];     // 512*1536
__device__ float g_wout[CC*CC];       // 512*512
__device__ float g_qkv[MTOT*QKVC];    // 4096*1536
__device__ float g_att[MTOT*CC];      // 4096*512

// ---------------------------------------------------------------------------
// Fold LoRA into effective weight
// ---------------------------------------------------------------------------
__global__ void fuse_w_kernel(const float* __restrict__ W,
                              const float* __restrict__ A,
                              const float* __restrict__ Bm,
                              float* __restrict__ out, int Nn) {
    int idx = blockIdx.x * blockDim.x + threadIdx.x;
    int total = CC * Nn;
    if (idx >= total) return;
    int i = idx / Nn;
    int j = idx - i * Nn;
    float acc = W[idx];
    #pragma unroll
    for (int r = 0; r < RR; r++)
        acc += LORA_SC * A[i*RR + r] * Bm[r*Nn + j];
    out[idx] = acc;
}

// ---------------------------------------------------------------------------
// tf32 mma.sync GEMM: C[M][N] = A[M][K]*B[K][N] (+bias)
// BM=128, BN=128, BK=32. 256 threads = 8 warps (4m x 2n), warp tile 32x64.
// ---------------------------------------------------------------------------
__device__ __forceinline__ uint32_t f2tf32(float f) {
    uint32_t r;
    asm volatile("cvt.rna.tf32.f32 %0, %1;" : "=r"(r) : "f"(f));
    return r;
}

#define GAST 36    // As word stride (BK+4)
#define GBST 136   // Bs word stride (BN+8) -> bank = 8k+g, conflict-free frags

__global__ __launch_bounds__(256, 2) void tf32_gemm(
    const float* __restrict__ A, const float* __restrict__ B,
    const float* __restrict__ bias, float* __restrict__ C,
    int M, int N, int K) {
    __shared__ uint32_t As[128 * GAST];
    __shared__ uint32_t Bs[32 * GBST];

    int tid = threadIdx.x;
    int warp = tid >> 5, lane = tid & 31;
    int wm = warp & 3, wn = warp >> 2;
    int g = lane >> 2, tig = lane & 3;
    int bm = blockIdx.y * 128;
    int bn = blockIdx.x * 128;

    float acc[2][8][4];
    #pragma unroll
    for (int im = 0; im < 2; im++)
        #pragma unroll
        for (int in = 0; in < 8; in++)
            #pragma unroll
            for (int c = 0; c < 4; c++) acc[im][in][c] = 0.f;

    // global-load register staging
    float4 areg[4], breg[4];

    // A tile: 128x32 floats = 1024 f4; thread i-th: idx=tid+256i, r=idx>>3, c4=idx&7
    // B tile: 32x128 floats = 1024 f4; r=idx>>5, c4=idx&31
    #pragma unroll
    for (int i = 0; i < 4; i++) {
        int idx = tid + 256*i;
        int ar = idx >> 3, ac4 = idx & 7;
        areg[i] = *(const float4*)&A[(size_t)(bm + ar) * K + ac4*4];
        int brr = idx >> 5, bc4 = idx & 31;
        breg[i] = *(const float4*)&B[(size_t)brr * N + bn + bc4*4];
    }

    for (int kt = 0; kt < K; kt += 32) {
        __syncthreads();
        #pragma unroll
        for (int i = 0; i < 4; i++) {
            int idx = tid + 256*i;
            int ar = idx >> 3, ac4 = idx & 7;
            uint4 av;
            av.x = f2tf32(areg[i].x); av.y = f2tf32(areg[i].y);
            av.z = f2tf32(areg[i].z); av.w = f2tf32(areg[i].w);
            *(uint4*)&As[ar*GAST + ac4*4] = av;
            int brr = idx >> 5, bc4 = idx & 31;
            uint4 bv;
            bv.x = f2tf32(breg[i].x); bv.y = f2tf32(breg[i].y);
            bv.z = f2tf32(breg[i].z); bv.w = f2tf32(breg[i].w);
            *(uint4*)&Bs[brr*GBST + bc4*4] = bv;
        }
        __syncthreads();

        if (kt + 32 < K) {
            #pragma unroll
            for (int i = 0; i < 4; i++) {
                int idx = tid + 256*i;
                int ar = idx >> 3, ac4 = idx & 7;
                areg[i] = *(const float4*)&A[(size_t)(bm + ar) * K + kt + 32 + ac4*4];
                int brr = idx >> 5, bc4 = idx & 31;
                breg[i] = *(const float4*)&B[(size_t)(kt + 32 + brr) * N + bn + bc4*4];
            }
        }

        #pragma unroll
        for (int kc = 0; kc < 4; kc++) {
            int k0 = kc * 8;
            uint32_t af[2][4];
            #pragma unroll
            for (int im = 0; im < 2; im++) {
                int rb = wm*32 + im*16;
                af[im][0] = As[(rb + g)*GAST + k0 + tig];
                af[im][1] = As[(rb + g + 8)*GAST + k0 + tig];
                af[im][2] = As[(rb + g)*GAST + k0 + tig + 4];
                af[im][3] = As[(rb + g + 8)*GAST + k0 + tig + 4];
            }
            uint32_t bf[8][2];
            #pragma unroll
            for (int in = 0; in < 8; in++) {
                int cb = wn*64 + in*8;
                bf[in][0] = Bs[(k0 + tig)*GBST + cb + g];
                bf[in][1] = Bs[(k0 + tig + 4)*GBST + cb + g];
            }
            #pragma unroll
            for (int im = 0; im < 2; im++)
                #pragma unroll
                for (int in = 0; in < 8; in++) {
                    asm volatile(
                        "mma.sync.aligned.m16n8k8.row.col.f32.tf32.tf32.f32 "
                        "{%0,%1,%2,%3}, {%4,%5,%6,%7}, {%8,%9}, {%0,%1,%2,%3};\n"
                        : "+f"(acc[im][in][0]), "+f"(acc[im][in][1]),
                          "+f"(acc[im][in][2]), "+f"(acc[im][in][3])
                        : "r"(af[im][0]), "r"(af[im][1]), "r"(af[im][2]), "r"(af[im][3]),
                          "r"(bf[in][0]), "r"(bf[in][1]));
                }
        }
    }

    // epilogue
    #pragma unroll
    for (int in = 0; in < 8; in++) {
        int col = bn + wn*64 + in*8 + tig*2;
        float b0 = 0.f, b1 = 0.f;
        if (bias) { b0 = bias[col]; b1 = bias[col+1]; }
        #pragma unroll
        for (int im = 0; im < 2; im++) {
            int row = bm + wm*32 + im*16 + g;
            float2 v0 = make_float2(acc[im][in][0] + b0, acc[im][in][1] + b1);
            float2 v1 = make_float2(acc[im][in][2] + b0, acc[im][in][3] + b1);
            *(float2*)&C[(size_t)row * N + col] = v0;
            *(float2*)&C[(size_t)(row + 8) * N + col] = v1;
        }
    }
}

// ---------------------------------------------------------------------------
// Attention: block = (64-query tile, head, batch). Register-tiled outer-product
// score + PV phases; transposed smem layouts; parallel softmax.
// ---------------------------------------------------------------------------
#define QTS 68      // Qt stride: Qt[k][q]
#define KTS 168     // Kt stride: Kt[k][j], j in [0,160)
#define VS  68      // V stride:  V[j][d]
#define SS  68      // S stride:  S[j][q]

#define OFF_QT  0
#define OFF_KT  (OFF_QT + 64*QTS)          // 4352
#define OFF_V   (OFF_KT + 64*KTS)          // 15104
#define OFF_S   (OFF_V  + 160*VS)          // 25984
#define OFF_RL  (OFF_S  + 160*SS)          // 36864  red local [4][64]
#define OFF_RG  (OFF_RL + 256)             // redG [4][64]
#define OFF_ML  (OFF_RG + 256)             // max local [64]
#define OFF_MG  (OFF_ML + 64)
#define OFF_IL  (OFF_MG + 64)              // inv local [64]
#define OFF_IG  (OFF_IL + 64)
#define ATT_SMEM_FLOATS (OFF_IG + 64)      // 37568 floats = 150272 B

__global__ __launch_bounds__(256) void attn_kernel(float* __restrict__ outp) {
    extern __shared__ float sm[];
    float* sQt = sm + OFF_QT;
    float* sKt = sm + OFF_KT;
    float* sV  = sm + OFF_V;
    float* sS  = sm + OFF_S;
    float* sRL = sm + OFF_RL;
    float* sRG = sm + OFF_RG;
    float* sML = sm + OFF_ML;
    float* sMG = sm + OFF_MG;
    float* sIL = sm + OFF_IL;
    float* sIG = sm + OFF_IG;

    const float* qkv = g_qkv;
    int qb = blockIdx.x, h = blockIdx.y, b = blockIdx.z;
    int tid = threadIdx.x;
    int qstart = qb * 64;
    const float scale = 0.125f;
    const float NEG = -1e30f;

    // ---- loads ----
    // Q transposed: Qt[k][q]
    for (int idx = tid; idx < 64*16; idx += 256) {
        int r = idx >> 4, c4 = idx & 15;
        float4 f = *(const float4*)&qkv[((size_t)(b*NN + qstart + r)) * QKVC + h*DH + c4*4];
        sQt[(4*c4+0)*QTS + r] = f.x;
        sQt[(4*c4+1)*QTS + r] = f.y;
        sQt[(4*c4+2)*QTS + r] = f.z;
        sQt[(4*c4+3)*QTS + r] = f.w;
    }
    // K transposed (Kt[k][j]) + V direct (V[j][d]); j<128 local, j>=128 global
    for (int idx = tid; idx < 160*16; idx += 256) {
        int r = idx >> 4, c4 = idx & 15;
        int kidx;
        if (r < 128) { kidx = qstart - 64 + r; if (kidx < 0) kidx = 0; }
        else         { kidx = (r - 128) * WIN; }
        size_t base = ((size_t)(b*NN + kidx)) * QKVC + h*DH + c4*4;
        float4 fk = *(const float4*)&qkv[base + CC];
        float4 fv = *(const float4*)&qkv[base + 2*CC];
        sKt[(4*c4+0)*KTS + r] = fk.x;
        sKt[(4*c4+1)*KTS + r] = fk.y;
        sKt[(4*c4+2)*KTS + r] = fk.z;
        sKt[(4*c4+3)*KTS + r] = fk.w;
        *(float4*)&sV[r*VS + c4*4] = fv;
    }
    __syncthreads();

    // ---- local scores: thread = 4q x 8k ----
    {
        int qg = tid & 15, kg = tid >> 4;    // qg*4 queries, kg*8 keys
        float a[4][8];
        #pragma unroll
        for (int i = 0; i < 4; i++)
            #pragma unroll
            for (int j = 0; j < 8; j++) a[i][j] = 0.f;
        for (int k = 0; k < 64; k++) {
            float4 qv = *(const float4*)&sQt[k*QTS + qg*4];
            float4 k0 = *(const float4*)&sKt[k*KTS + kg*8];
            float4 k1 = *(const float4*)&sKt[k*KTS + kg*8 + 4];
            float qa[4] = {qv.x, qv.y, qv.z, qv.w};
            float kk[8] = {k0.x, k0.y, k0.z, k0.w, k1.x, k1.y, k1.z, k1.w};
            #pragma unroll
            for (int i = 0; i < 4; i++)
                #pragma unroll
                for (int j = 0; j < 8; j++)
                    a[i][j] += qa[i] * kk[j];
        }
        #pragma unroll
        for (int j = 0; j < 8; j++) {
            int jj = kg*8 + j;
            float4 o;
            float* op = (float*)&o;
            #pragma unroll
            for (int i = 0; i < 4; i++) {
                int qi = qg*4 + i;
                bool valid = (jj >= qi) && (jj <= qi + 64) && (jj >= 64 - qstart);
                op[i] = valid ? a[i][j] * scale : NEG;
            }
            *(float4*)&sS[jj*SS + qg*4] = o;
        }
    }
    // ---- global scores: thread = 4q x 2k ----
    {
        int qg = tid & 15, kg = tid >> 4;    // keys 128 + kg*2
        float a[4][2];
        #pragma unroll
        for (int i = 0; i < 4; i++) { a[i][0] = 0.f; a[i][1] = 0.f; }
        for (int k = 0; k < 64; k++) {
            float4 qv = *(const float4*)&sQt[k*QTS + qg*4];
            float2 kk = *(const float2*)&sKt[k*KTS + 128 + kg*2];
            float qa[4] = {qv.x, qv.y, qv.z, qv.w};
            #pragma unroll
            for (int i = 0; i < 4; i++) {
                a[i][0] += qa[i] * kk.x;
                a[i][1] += qa[i] * kk.y;
            }
        }
        #pragma unroll
        for (int j = 0; j < 2; j++) {
            int jj = 128 + kg*2 + j;
            float4 o = make_float4(a[0][j]*scale, a[1][j]*scale, a[2][j]*scale, a[3][j]*scale);
            *(float4*)&sS[jj*SS + qg*4] = o;
        }
    }
    __syncthreads();

    // ---- softmax: part = tid>>6 (4 parts), q = tid&63 ----
    {
        int part = tid >> 6, q = tid & 63;
        float m = NEG;
        for (int jj = 0; jj < 32; jj++)
            m = fmaxf(m, sS[(part*32 + jj)*SS + q]);
        sRL[part*64 + q] = m;
        float mg = NEG;
        for (int jj = 0; jj < 8; jj++)
            mg = fmaxf(mg, sS[(128 + part*8 + jj)*SS + q]);
        sRG[part*64 + q] = mg;
    }
    __syncthreads();
    if (tid < 64) {
        int q = tid;
        sML[q] = fmaxf(fmaxf(sRL[q], sRL[64+q]), fmaxf(sRL[128+q], sRL[192+q]));
        sMG[q] = fmaxf(fmaxf(sRG[q], sRG[64+q]), fmaxf(sRG[128+q], sRG[192+q]));
    }
    __syncthreads();
    {
        int part = tid >> 6, q = tid & 63;
        float mL = sML[q], mG = sMG[q];
        float s = 0.f;
        for (int jj = 0; jj < 32; jj++) {
            int j = part*32 + jj;
            float e = __expf(sS[j*SS + q] - mL);
            sS[j*SS + q] = e;
            s += e;
        }
        sRL[part*64 + q] = s;
        float sg = 0.f;
        for (int jj = 0; jj < 8; jj++) {
            int j = 128 + part*8 + jj;
            float e = __expf(sS[j*SS + q] - mG);
            sS[j*SS + q] = e;
            sg += e;
        }
        sRG[part*64 + q] = sg;
    }
    __syncthreads();
    if (tid < 64) {
        int q = tid;
        sIL[q] = 1.f / (sRL[q] + sRL[64+q] + sRL[128+q] + sRL[192+q]);
        sIG[q] = 1.f / (sRG[q] + sRG[64+q] + sRG[128+q] + sRG[192+q]);
    }
    __syncthreads();

    // ---- PV: thread = 4q x 4dh ----
    {
        int qg = tid & 15, dg = tid >> 4;
        float4 oL[4], oG[4];
        #pragma unroll
        for (int i = 0; i < 4; i++) {
            oL[i] = make_float4(0,0,0,0);
            oG[i] = make_float4(0,0,0,0);
        }
        for (int j = 0; j < 128; j++) {
            float4 p = *(const float4*)&sS[j*SS + qg*4];
            float4 v = *(const float4*)&sV[j*VS + dg*4];
            float pa[4] = {p.x, p.y, p.z, p.w};
            #pragma unroll
            for (int i = 0; i < 4; i++) {
                oL[i].x += pa[i]*v.x; oL[i].y += pa[i]*v.y;
                oL[i].z += pa[i]*v.z; oL[i].w += pa[i]*v.w;
            }
        }
        for (int j = 128; j < 160; j++) {
            float4 p = *(const float4*)&sS[j*SS + qg*4];
            float4 v = *(const float4*)&sV[j*VS + dg*4];
            float pa[4] = {p.x, p.y, p.z, p.w};
            #pragma unroll
            for (int i = 0; i < 4; i++) {
                oG[i].x += pa[i]*v.x; oG[i].y += pa[i]*v.y;
                oG[i].z += pa[i]*v.z; oG[i].w += pa[i]*v.w;
            }
        }
        #pragma unroll
        for (int i = 0; i < 4; i++) {
            int q = qg*4 + i;
            float il = sIL[q], ig = sIG[q];
            float4 o;
            o.x = oL[i].x*il + oG[i].x*ig;
            o.y = oL[i].y*il + oG[i].y*ig;
            o.z = oL[i].z*il + oG[i].z*ig;
            o.w = oL[i].w*il + oG[i].w*ig;
            *(float4*)&g_att[((size_t)(b*NN + qstart + q)) * CC + h*DH + dg*4] = o;
        }
    }
}

// ---------------------------------------------------------------------------
// launch
// ---------------------------------------------------------------------------
extern "C" void kernel_launch(void* const* d_in, const int* in_sizes, int n_in,
                              void* d_out, int out_size) {
    const float* x       = (const float*)d_in[0];
    const float* w_qkv   = (const float*)d_in[1];
    const float* lA_qkv  = (const float*)d_in[2];
    const float* lB_qkv  = (const float*)d_in[3];
    const float* w_out   = (const float*)d_in[4];
    const float* b_out   = (const float*)d_in[5];
    const float* lA_out  = (const float*)d_in[6];
    const float* lB_out  = (const float*)d_in[7];
    float* out = (float*)d_out;

    float *p_weff, *p_wout, *p_qkv, *p_att;
    cudaGetSymbolAddress((void**)&p_weff, g_weff);
    cudaGetSymbolAddress((void**)&p_wout, g_wout);
    cudaGetSymbolAddress((void**)&p_qkv,  g_qkv);
    cudaGetSymbolAddress((void**)&p_att,  g_att);

    // 1. fold LoRA into effective weights
    fuse_w_kernel<<<(CC*QKVC + 255)/256, 256>>>(w_qkv, lA_qkv, lB_qkv, p_weff, QKVC);
    fuse_w_kernel<<<(CC*CC + 255)/256, 256>>>(w_out, lA_out, lB_out, p_wout, CC);

    // 2. qkv = x @ w_eff   (tf32 tensor GEMM)
    {
        dim3 grid(QKVC/128, MTOT/128);
        tf32_gemm<<<grid, 256>>>(x, p_weff, nullptr, p_qkv, MTOT, QKVC, CC);
    }
    // 3. attention
    {
        size_t smem_bytes = ATT_SMEM_FLOATS * sizeof(float);
        cudaFuncSetAttribute(attn_kernel, cudaFuncAttributeMaxDynamicSharedMemorySize,
                             (int)smem_bytes);
        dim3 grid(NN/64, HEADS, BB);
        attn_kernel<<<grid, 256, smem_bytes>>>(p_att);
    }
    // 4. out = att @ w_out_eff + b_out   (tf32 tensor GEMM)
    {
        dim3 grid(CC/128, MTOT/128);
        tf32_gemm<<<grid, 256>>>(p_att, p_wout, b_out, out, MTOT, CC, CC);
    }
}

// round 3
// speedup vs baseline: 3.1229x; 1.2537x over previous
#include <cuda_runtime.h>
#include <cuda_bf16.h>
#include <math.h>
#include <stdint.h>

// Problem constants
#define BB   2
#define NN   2048
#define CC   512
#define HEADS 8
#define DH   64
#define WIN  64
#define RR   8
#define MTOT (BB*NN)        // 4096
#define QKVC (3*CC)         // 1536
#define LORA_SC 0.25f

// Scratch (device globals)
__device__ float g_weff[CC*QKVC];
__device__ float g_wout[CC*CC];
__device__ float g_qkv[MTOT*QKVC];
__device__ float g_att[MTOT*CC];

__device__ __forceinline__ uint32_t f2tf32(float f) {
    uint32_t r;
    asm volatile("cvt.rna.tf32.f32 %0, %1;" : "=r"(r) : "f"(f));
    return r;
}

#define MMA_TF32(acc, a0,a1,a2,a3, b0,b1)                                     \
    asm volatile(                                                              \
        "mma.sync.aligned.m16n8k8.row.col.f32.tf32.tf32.f32 "                  \
        "{%0,%1,%2,%3}, {%4,%5,%6,%7}, {%8,%9}, {%0,%1,%2,%3};\n"              \
        : "+f"(acc[0]), "+f"(acc[1]), "+f"(acc[2]), "+f"(acc[3])               \
        : "r"(a0), "r"(a1), "r"(a2), "r"(a3), "r"(b0), "r"(b1))

// ---------------------------------------------------------------------------
// Fold LoRA into both effective weights (one launch)
// ---------------------------------------------------------------------------
__global__ void fuse_w_kernel(const float* __restrict__ Wq,
                              const float* __restrict__ Aq,
                              const float* __restrict__ Bq,
                              const float* __restrict__ Wo,
                              const float* __restrict__ Ao,
                              const float* __restrict__ Bo) {
    int idx = blockIdx.x * blockDim.x + threadIdx.x;
    if (idx < CC*QKVC) {
        int i = idx / QKVC, j = idx - i*QKVC;
        float acc = Wq[idx];
        #pragma unroll
        for (int r = 0; r < RR; r++)
            acc += LORA_SC * Aq[i*RR + r] * Bq[r*QKVC + j];
        g_weff[idx] = acc;
    } else {
        int k = idx - CC*QKVC;
        if (k < CC*CC) {
            int i = k / CC, j = k - i*CC;
            float acc = Wo[k];
            #pragma unroll
            for (int r = 0; r < RR; r++)
                acc += LORA_SC * Ao[i*RR + r] * Bo[r*CC + j];
            g_wout[k] = acc;
        }
    }
}

// ---------------------------------------------------------------------------
// tf32 mma GEMM (as R2): BM=BN=128, BK=32, 256 thr, warp tile 32x64
// ---------------------------------------------------------------------------
#define GAST 36
#define GBST 136

__global__ __launch_bounds__(256, 2) void tf32_gemm(
    const float* __restrict__ A, const float* __restrict__ B,
    const float* __restrict__ bias, float* __restrict__ C,
    int M, int N, int K) {
    __shared__ uint32_t As[128 * GAST];
    __shared__ uint32_t Bs[32 * GBST];

    int tid = threadIdx.x;
    int warp = tid >> 5, lane = tid & 31;
    int wm = warp & 3, wn = warp >> 2;
    int g = lane >> 2, tig = lane & 3;
    int bm = blockIdx.y * 128;
    int bn = blockIdx.x * 128;

    float acc[2][8][4];
    #pragma unroll
    for (int im = 0; im < 2; im++)
        #pragma unroll
        for (int in = 0; in < 8; in++)
            #pragma unroll
            for (int c = 0; c < 4; c++) acc[im][in][c] = 0.f;

    float4 areg[4], breg[4];
    #pragma unroll
    for (int i = 0; i < 4; i++) {
        int idx = tid + 256*i;
        int ar = idx >> 3, ac4 = idx & 7;
        areg[i] = *(const float4*)&A[(size_t)(bm + ar) * K + ac4*4];
        int brr = idx >> 5, bc4 = idx & 31;
        breg[i] = *(const float4*)&B[(size_t)brr * N + bn + bc4*4];
    }

    for (int kt = 0; kt < K; kt += 32) {
        __syncthreads();
        #pragma unroll
        for (int i = 0; i < 4; i++) {
            int idx = tid + 256*i;
            int ar = idx >> 3, ac4 = idx & 7;
            uint4 av;
            av.x = f2tf32(areg[i].x); av.y = f2tf32(areg[i].y);
            av.z = f2tf32(areg[i].z); av.w = f2tf32(areg[i].w);
            *(uint4*)&As[ar*GAST + ac4*4] = av;
            int brr = idx >> 5, bc4 = idx & 31;
            uint4 bv;
            bv.x = f2tf32(breg[i].x); bv.y = f2tf32(breg[i].y);
            bv.z = f2tf32(breg[i].z); bv.w = f2tf32(breg[i].w);
            *(uint4*)&Bs[brr*GBST + bc4*4] = bv;
        }
        __syncthreads();

        if (kt + 32 < K) {
            #pragma unroll
            for (int i = 0; i < 4; i++) {
                int idx = tid + 256*i;
                int ar = idx >> 3, ac4 = idx & 7;
                areg[i] = *(const float4*)&A[(size_t)(bm + ar) * K + kt + 32 + ac4*4];
                int brr = idx >> 5, bc4 = idx & 31;
                breg[i] = *(const float4*)&B[(size_t)(kt + 32 + brr) * N + bn + bc4*4];
            }
        }

        #pragma unroll
        for (int kc = 0; kc < 4; kc++) {
            int k0 = kc * 8;
            uint32_t af[2][4];
            #pragma unroll
            for (int im = 0; im < 2; im++) {
                int rb = wm*32 + im*16;
                af[im][0] = As[(rb + g)*GAST + k0 + tig];
                af[im][1] = As[(rb + g + 8)*GAST + k0 + tig];
                af[im][2] = As[(rb + g)*GAST + k0 + tig + 4];
                af[im][3] = As[(rb + g + 8)*GAST + k0 + tig + 4];
            }
            uint32_t bf[8][2];
            #pragma unroll
            for (int in = 0; in < 8; in++) {
                int cb = wn*64 + in*8;
                bf[in][0] = Bs[(k0 + tig)*GBST + cb + g];
                bf[in][1] = Bs[(k0 + tig + 4)*GBST + cb + g];
            }
            #pragma unroll
            for (int im = 0; im < 2; im++)
                #pragma unroll
                for (int in = 0; in < 8; in++)
                    MMA_TF32(acc[im][in], af[im][0], af[im][1], af[im][2], af[im][3],
                             bf[in][0], bf[in][1]);
        }
    }

    #pragma unroll
    for (int in = 0; in < 8; in++) {
        int col = bn + wn*64 + in*8 + tig*2;
        float b0 = 0.f, b1 = 0.f;
        if (bias) { b0 = bias[col]; b1 = bias[col+1]; }
        #pragma unroll
        for (int im = 0; im < 2; im++) {
            int row = bm + wm*32 + im*16 + g;
            float2 v0 = make_float2(acc[im][in][0] + b0, acc[im][in][1] + b1);
            float2 v1 = make_float2(acc[im][in][2] + b0, acc[im][in][3] + b1);
            *(float2*)&C[(size_t)row * N + col] = v0;
            *(float2*)&C[(size_t)(row + 8) * N + col] = v1;
        }
    }
}

// ---------------------------------------------------------------------------
// Attention via tf32 mma. Block = (64-query tile, head, batch).
// Scores: [64 x 160] = Q[64x64] x Kt ; PV: [64x64] = P[64x160] x V[160x64]
// Softmax in registers; P region aliases Q/K region.
// ---------------------------------------------------------------------------
#define AT_QS 68    // sQ[q][d] stride (%32==4 -> conflict-free A frags)
#define AT_KS 168   // sKt[d][j] stride (%32==8 -> conflict-free B frags)
#define AT_VS 72    // sV[j][d] stride (%32==8)
#define AT_SS 164   // sP[q][j] stride (%32==4)

#define AOFF_V   0
#define AOFF_RED (AOFF_V + 160*AT_VS)        // 384 words
#define R_ML 0     // maxL parts [2][64]
#define R_MG 128   // maxG [64]
#define R_SL 192   // sumL parts [2][64]
#define R_SG 320   // sumG [64]
#define AOFF_Q   (AOFF_RED + 384)
#define AOFF_K   (AOFF_Q + 64*AT_QS)
#define AOFF_S   AOFF_Q                      // aliases Q..K (10496 <= 15104)
#define ATT_WORDS (AOFF_K + 64*AT_KS)        // 27008 words = 108032 B

__global__ __launch_bounds__(256, 2) void attn_kernel() {
    extern __shared__ uint32_t sm[];
    float* smf = (float*)sm;

    const float* qkv = g_qkv;
    int qb = blockIdx.x, h = blockIdx.y, b = blockIdx.z;
    int tid = threadIdx.x;
    int warp = tid >> 5, lane = tid & 31;
    int g = lane >> 2, tig = lane & 3;
    int wm = warp & 3, wn = warp >> 2;
    int qstart = qb * 64;
    const float NEG = -1e30f;

    // ---- loads (convert to tf32) ----
    for (int idx = tid; idx < 64*16; idx += 256) {
        int r = idx >> 4, c4 = idx & 15;
        float4 f = *(const float4*)&qkv[((size_t)(b*NN + qstart + r)) * QKVC + h*DH + c4*4];
        uint4 u;
        u.x = f2tf32(f.x); u.y = f2tf32(f.y); u.z = f2tf32(f.z); u.w = f2tf32(f.w);
        *(uint4*)&sm[AOFF_Q + r*AT_QS + c4*4] = u;
    }
    for (int idx = tid; idx < 160*16; idx += 256) {
        int r = idx >> 4, c4 = idx & 15;
        int kidx;
        if (r < 128) { kidx = qstart - 64 + r; if (kidx < 0) kidx = 0; }
        else         { kidx = (r - 128) * WIN; }
        size_t base = ((size_t)(b*NN + kidx)) * QKVC + h*DH + c4*4;
        float4 fk = *(const float4*)&qkv[base + CC];
        float4 fv = *(const float4*)&qkv[base + 2*CC];
        sm[AOFF_K + (4*c4+0)*AT_KS + r] = f2tf32(fk.x);
        sm[AOFF_K + (4*c4+1)*AT_KS + r] = f2tf32(fk.y);
        sm[AOFF_K + (4*c4+2)*AT_KS + r] = f2tf32(fk.z);
        sm[AOFF_K + (4*c4+3)*AT_KS + r] = f2tf32(fk.w);
        uint4 uv;
        uv.x = f2tf32(fv.x); uv.y = f2tf32(fv.y); uv.z = f2tf32(fv.z); uv.w = f2tf32(fv.w);
        *(uint4*)&sm[AOFF_V + r*AT_VS + c4*4] = uv;
    }
    __syncthreads();

    // ---- score mma: warp tile 16m x 80n, k=64 ----
    float acc[10][4];
    #pragma unroll
    for (int n = 0; n < 10; n++)
        #pragma unroll
        for (int c = 0; c < 4; c++) acc[n][c] = 0.f;

    int row0 = wm*16 + g, row1 = row0 + 8;
    #pragma unroll
    for (int ks = 0; ks < 8; ks++) {
        int k0 = ks * 8;
        uint32_t a0 = sm[AOFF_Q + row0*AT_QS + k0 + tig];
        uint32_t a1 = sm[AOFF_Q + row1*AT_QS + k0 + tig];
        uint32_t a2 = sm[AOFF_Q + row0*AT_QS + k0 + tig + 4];
        uint32_t a3 = sm[AOFF_Q + row1*AT_QS + k0 + tig + 4];
        #pragma unroll
        for (int n = 0; n < 10; n++) {
            int cb = wn*80 + n*8;
            uint32_t b0 = sm[AOFF_K + (k0 + tig)*AT_KS + cb + g];
            uint32_t b1 = sm[AOFF_K + (k0 + tig + 4)*AT_KS + cb + g];
            MMA_TF32(acc[n], a0, a1, a2, a3, b0, b1);
        }
    }

    // ---- mask + scale (registers) ----
    int minj = 64 - qstart;   // j >= minj required for valid local key
    #pragma unroll
    for (int n = 0; n < 10; n++) {
        int cb = wn*80 + n*8;
        int c0 = cb + tig*2, c1 = c0 + 1;
        if (cb < 128) {  // local columns (entire 8-col tile is local: cb+7 <= 127)
            bool v00 = (c0 >= row0) && (c0 <= row0 + 64) && (c0 >= minj);
            bool v01 = (c1 >= row0) && (c1 <= row0 + 64) && (c1 >= minj);
            bool v10 = (c0 >= row1) && (c0 <= row1 + 64) && (c0 >= minj);
            bool v11 = (c1 >= row1) && (c1 <= row1 + 64) && (c1 >= minj);
            acc[n][0] = v00 ? acc[n][0]*0.125f : NEG;
            acc[n][1] = v01 ? acc[n][1]*0.125f : NEG;
            acc[n][2] = v10 ? acc[n][2]*0.125f : NEG;
            acc[n][3] = v11 ? acc[n][3]*0.125f : NEG;
        } else {         // global columns
            acc[n][0] *= 0.125f; acc[n][1] *= 0.125f;
            acc[n][2] *= 0.125f; acc[n][3] *= 0.125f;
        }
    }

    // ---- softmax: register partials + quad shuffles + smem combine ----
    int nLoc = (wn == 0) ? 10 : 6;   // wn=0: cols 0..79 local; wn=1: tiles 0..5 local
    float m0 = NEG, m1 = NEG;
    for (int n = 0; n < nLoc; n++) {
        m0 = fmaxf(m0, fmaxf(acc[n][0], acc[n][1]));
        m1 = fmaxf(m1, fmaxf(acc[n][2], acc[n][3]));
    }
    m0 = fmaxf(m0, __shfl_xor_sync(0xffffffffu, m0, 1));
    m0 = fmaxf(m0, __shfl_xor_sync(0xffffffffu, m0, 2));
    m1 = fmaxf(m1, __shfl_xor_sync(0xffffffffu, m1, 1));
    m1 = fmaxf(m1, __shfl_xor_sync(0xffffffffu, m1, 2));
    float mg0 = NEG, mg1 = NEG;
    if (wn == 1) {
        for (int n = 6; n < 10; n++) {
            mg0 = fmaxf(mg0, fmaxf(acc[n][0], acc[n][1]));
            mg1 = fmaxf(mg1, fmaxf(acc[n][2], acc[n][3]));
        }
        mg0 = fmaxf(mg0, __shfl_xor_sync(0xffffffffu, mg0, 1));
        mg0 = fmaxf(mg0, __shfl_xor_sync(0xffffffffu, mg0, 2));
        mg1 = fmaxf(mg1, __shfl_xor_sync(0xffffffffu, mg1, 1));
        mg1 = fmaxf(mg1, __shfl_xor_sync(0xffffffffu, mg1, 2));
    }
    if (tig == 0) {
        smf[AOFF_RED + R_ML + wn*64 + row0] = m0;
        smf[AOFF_RED + R_ML + wn*64 + row1] = m1;
        if (wn == 1) {
            smf[AOFF_RED + R_MG + row0] = mg0;
            smf[AOFF_RED + R_MG + row1] = mg1;
        }
    }
    __syncthreads();   // also guarantees all mma reads of sQ/sK are done

    float mL0 = fmaxf(smf[AOFF_RED + R_ML + row0], smf[AOFF_RED + R_ML + 64 + row0]);
    float mL1 = fmaxf(smf[AOFF_RED + R_ML + row1], smf[AOFF_RED + R_ML + 64 + row1]);
    float mG0 = smf[AOFF_RED + R_MG + row0];
    float mG1 = smf[AOFF_RED + R_MG + row1];

    float s0 = 0.f, s1 = 0.f, sg0 = 0.f, sg1 = 0.f;
    for (int n = 0; n < nLoc; n++) {
        acc[n][0] = __expf(acc[n][0] - mL0); s0 += acc[n][0];
        acc[n][1] = __expf(acc[n][1] - mL0); s0 += acc[n][1];
        acc[n][2] = __expf(acc[n][2] - mL1); s1 += acc[n][2];
        acc[n][3] = __expf(acc[n][3] - mL1); s1 += acc[n][3];
    }
    if (wn == 1) {
        for (int n = 6; n < 10; n++) {
            acc[n][0] = __expf(acc[n][0] - mG0); sg0 += acc[n][0];
            acc[n][1] = __expf(acc[n][1] - mG0); sg0 += acc[n][1];
            acc[n][2] = __expf(acc[n][2] - mG1); sg1 += acc[n][2];
            acc[n][3] = __expf(acc[n][3] - mG1); sg1 += acc[n][3];
        }
    }
    s0 += __shfl_xor_sync(0xffffffffu, s0, 1);
    s0 += __shfl_xor_sync(0xffffffffu, s0, 2);
    s1 += __shfl_xor_sync(0xffffffffu, s1, 1);
    s1 += __shfl_xor_sync(0xffffffffu, s1, 2);
    if (wn == 1) {
        sg0 += __shfl_xor_sync(0xffffffffu, sg0, 1);
        sg0 += __shfl_xor_sync(0xffffffffu, sg0, 2);
        sg1 += __shfl_xor_sync(0xffffffffu, sg1, 1);
        sg1 += __shfl_xor_sync(0xffffffffu, sg1, 2);
    }
    if (tig == 0) {
        smf[AOFF_RED + R_SL + wn*64 + row0] = s0;
        smf[AOFF_RED + R_SL + wn*64 + row1] = s1;
        if (wn == 1) {
            smf[AOFF_RED + R_SG + row0] = sg0;
            smf[AOFF_RED + R_SG + row1] = sg1;
        }
    }
    __syncthreads();

    float iL0 = 1.f / (smf[AOFF_RED + R_SL + row0] + smf[AOFF_RED + R_SL + 64 + row0]);
    float iL1 = 1.f / (smf[AOFF_RED + R_SL + row1] + smf[AOFF_RED + R_SL + 64 + row1]);
    float iG0 = 1.f / smf[AOFF_RED + R_SG + row0];
    float iG1 = 1.f / smf[AOFF_RED + R_SG + row1];

    // normalize + write P (tf32) into aliased region
    #pragma unroll
    for (int n = 0; n < 10; n++) {
        int cb = wn*80 + n*8;
        int c0 = cb + tig*2;
        float f0, f1, f2, f3;
        if (n < nLoc || wn == 0) { f0 = acc[n][0]*iL0; f1 = acc[n][1]*iL0;
                                   f2 = acc[n][2]*iL1; f3 = acc[n][3]*iL1; }
        else                     { f0 = acc[n][0]*iG0; f1 = acc[n][1]*iG0;
                                   f2 = acc[n][2]*iG1; f3 = acc[n][3]*iG1; }
        sm[AOFF_S + row0*AT_SS + c0]     = f2tf32(f0);
        sm[AOFF_S + row0*AT_SS + c0 + 1] = f2tf32(f1);
        sm[AOFF_S + row1*AT_SS + c0]     = f2tf32(f2);
        sm[AOFF_S + row1*AT_SS + c0 + 1] = f2tf32(f3);
    }
    __syncthreads();

    // ---- PV mma: warp tile 16m x 32n, k=160 ----
    float acc2[4][4];
    #pragma unroll
    for (int n = 0; n < 4; n++)
        #pragma unroll
        for (int c = 0; c < 4; c++) acc2[n][c] = 0.f;

    #pragma unroll
    for (int ks = 0; ks < 20; ks++) {
        int k0 = ks * 8;
        uint32_t a0 = sm[AOFF_S + row0*AT_SS + k0 + tig];
        uint32_t a1 = sm[AOFF_S + row1*AT_SS + k0 + tig];
        uint32_t a2 = sm[AOFF_S + row0*AT_SS + k0 + tig + 4];
        uint32_t a3 = sm[AOFF_S + row1*AT_SS + k0 + tig + 4];
        #pragma unroll
        for (int n = 0; n < 4; n++) {
            int cb = wn*32 + n*8;
            uint32_t b0 = sm[AOFF_V + (k0 + tig)*AT_VS + cb + g];
            uint32_t b1 = sm[AOFF_V + (k0 + tig + 4)*AT_VS + cb + g];
            MMA_TF32(acc2[n], a0, a1, a2, a3, b0, b1);
        }
    }

    // ---- output ----
    #pragma unroll
    for (int n = 0; n < 4; n++) {
        int col = h*DH + wn*32 + n*8 + tig*2;
        size_t r0o = ((size_t)(b*NN + qstart + row0)) * CC + col;
        size_t r1o = ((size_t)(b*NN + qstart + row1)) * CC + col;
        *(float2*)&g_att[r0o] = make_float2(acc2[n][0], acc2[n][1]);
        *(float2*)&g_att[r1o] = make_float2(acc2[n][2], acc2[n][3]);
    }
}

// ---------------------------------------------------------------------------
// launch
// ---------------------------------------------------------------------------
extern "C" void kernel_launch(void* const* d_in, const int* in_sizes, int n_in,
                              void* d_out, int out_size) {
    const float* x       = (const float*)d_in[0];
    const float* w_qkv   = (const float*)d_in[1];
    const float* lA_qkv  = (const float*)d_in[2];
    const float* lB_qkv  = (const float*)d_in[3];
    const float* w_out   = (const float*)d_in[4];
    const float* b_out   = (const float*)d_in[5];
    const float* lA_out  = (const float*)d_in[6];
    const float* lB_out  = (const float*)d_in[7];
    float* out = (float*)d_out;

    float *p_weff, *p_wout, *p_qkv, *p_att;
    cudaGetSymbolAddress((void**)&p_weff, g_weff);
    cudaGetSymbolAddress((void**)&p_wout, g_wout);
    cudaGetSymbolAddress((void**)&p_qkv,  g_qkv);
    cudaGetSymbolAddress((void**)&p_att,  g_att);

    // 1. fold LoRA into effective weights (single launch)
    {
        int total = CC*QKVC + CC*CC;
        fuse_w_kernel<<<(total + 255)/256, 256>>>(w_qkv, lA_qkv, lB_qkv,
                                                  w_out, lA_out, lB_out);
    }
    // 2. qkv = x @ w_eff
    {
        dim3 grid(QKVC/128, MTOT/128);
        tf32_gemm<<<grid, 256>>>(x, p_weff, nullptr, p_qkv, MTOT, QKVC, CC);
    }
    // 3. attention (tensor-core)
    {
        size_t smem_bytes = ATT_WORDS * sizeof(uint32_t);
        cudaFuncSetAttribute(attn_kernel, cudaFuncAttributeMaxDynamicSharedMemorySize,
                             (int)smem_bytes);
        dim3 grid(NN/64, HEADS, BB);
        attn_kernel<<<grid, 256, smem_bytes>>>();
    }
    // 4. out = att @ w_out_eff + b_out
    {
        dim3 grid(CC/128, MTOT/128);
        tf32_gemm<<<grid, 256>>>(p_att, p_wout, b_out, out, MTOT, CC, CC);
    }
}

// round 4
// speedup vs baseline: 3.3747x; 1.0806x over previous
#include <cuda_runtime.h>
#include <cuda_bf16.h>
#include <math.h>
#include <stdint.h>

// Problem constants
#define BB   2
#define NN   2048
#define CC   512
#define HEADS 8
#define DH   64
#define WIN  64
#define RR   8
#define MTOT (BB*NN)        // 4096
#define QKVC (3*CC)         // 1536
#define LORA_SC 0.25f

// Scratch (device globals)
__device__ float g_weff[QKVC*CC];   // effective W_qkv, TRANSPOSED [n][k], tf32-rounded
__device__ float g_wout[CC*CC];     // effective W_out, TRANSPOSED [n][k], tf32-rounded
__device__ float g_xr[MTOT*CC];     // x, tf32-rounded
__device__ float g_qkv[MTOT*QKVC];  // gemm1 output, tf32-rounded
__device__ float g_att[MTOT*CC];    // attention output, tf32-rounded

__device__ __forceinline__ uint32_t f2tf32(float f) {
    uint32_t r;
    asm volatile("cvt.rna.tf32.f32 %0, %1;" : "=r"(r) : "f"(f));
    return r;
}
__device__ __forceinline__ float rnd_tf32(float f) { return __uint_as_float(f2tf32(f)); }

__device__ __forceinline__ void cp16(uint32_t saddr, const void* gptr) {
    asm volatile("cp.async.ca.shared.global [%0], [%1], 16;\n" :: "r"(saddr), "l"(gptr));
}
#define CP_COMMIT asm volatile("cp.async.commit_group;\n" ::: "memory")
#define CP_WAIT(n) asm volatile("cp.async.wait_group %0;\n" :: "n"(n) : "memory")

#define MMA_TF32(acc, a0,a1,a2,a3, b0,b1)                                     \
    asm volatile(                                                              \
        "mma.sync.aligned.m16n8k8.row.col.f32.tf32.tf32.f32 "                  \
        "{%0,%1,%2,%3}, {%4,%5,%6,%7}, {%8,%9}, {%0,%1,%2,%3};\n"              \
        : "+f"(acc[0]), "+f"(acc[1]), "+f"(acc[2]), "+f"(acc[3])               \
        : "r"(a0), "r"(a1), "r"(a2), "r"(a3), "r"(b0), "r"(b1))

// ---------------------------------------------------------------------------
// Prep: fold LoRA into transposed tf32-rounded effective weights; round x.
// ---------------------------------------------------------------------------
__global__ void prep_kernel(const float* __restrict__ x,
                            const float* __restrict__ Wq,
                            const float* __restrict__ Aq,
                            const float* __restrict__ Bq,
                            const float* __restrict__ Wo,
                            const float* __restrict__ Ao,
                            const float* __restrict__ Bo) {
    int idx = blockIdx.x * blockDim.x + threadIdx.x;
    if (idx < QKVC*CC) {
        int j = idx / CC, i = idx - j*CC;      // weffT[j][i]
        float acc = Wq[i*QKVC + j];
        #pragma unroll
        for (int r = 0; r < RR; r++)
            acc += LORA_SC * Aq[i*RR + r] * Bq[r*QKVC + j];
        g_weff[idx] = rnd_tf32(acc);
    } else if (idx < QKVC*CC + CC*CC) {
        int k = idx - QKVC*CC;
        int j = k / CC, i = k - j*CC;          // woutT[j][i]
        float acc = Wo[i*CC + j];
        #pragma unroll
        for (int r = 0; r < RR; r++)
            acc += LORA_SC * Ao[i*RR + r] * Bo[r*CC + j];
        g_wout[k] = rnd_tf32(acc);
    } else {
        int v = idx - (QKVC*CC + CC*CC);       // float4 index into x
        float4 f = *(const float4*)&x[(size_t)v*4];
        f.x = rnd_tf32(f.x); f.y = rnd_tf32(f.y);
        f.z = rnd_tf32(f.z); f.w = rnd_tf32(f.w);
        *(float4*)&g_xr[(size_t)v*4] = f;
    }
}

// ---------------------------------------------------------------------------
// tf32 mma GEMM, cp.async double-buffered, LDS.128 fragment loads.
// C[M][N] = A[M][K] * Bt[N][K]^T (+bias). Inputs pre-rounded to tf32.
// BN=128, BK=32; BM template (128 or 64). 256 threads = 8 warps.
// k-position mapping: group kc in {0..3}: pos tig -> k=8*tig+2*kc, pos tig+4 -> +1
// ---------------------------------------------------------------------------
template<int BM, bool ROUND>
__global__ __launch_bounds__(256, 2) void tf32_gemm(
    const float* __restrict__ A, const float* __restrict__ Bt,
    const float* __restrict__ bias, float* __restrict__ C,
    int M, int N, int K) {
    constexpr int WM = BM/32;        // warps along m
    constexpr int WN = 8/WM;         // warps along n
    constexpr int NT = 128/(WN*8);   // 8-col n-tiles per warp
    constexpr int ACH = BM/32;       // A cp.async chunks per thread
    constexpr int AW = BM*36;        // words per A stage
    constexpr int BW = 128*36;       // words per B stage

    extern __shared__ uint32_t smg[];
    uint32_t smbase = (uint32_t)__cvta_generic_to_shared(smg);

    int tid = threadIdx.x;
    int warp = tid >> 5, lane = tid & 31;
    int wm = warp % WM, wn = warp / WM;
    int g = lane >> 2, tig = lane & 3;
    int bm = blockIdx.y * BM;
    int bn = blockIdx.x * 128;

    float acc[2][NT][4];
    #pragma unroll
    for (int im = 0; im < 2; im++)
        #pragma unroll
        for (int nt = 0; nt < NT; nt++)
            #pragma unroll
            for (int c = 0; c < 4; c++) acc[im][nt][c] = 0.f;

    auto issue = [&](int ktc, int s) {
        #pragma unroll
        for (int i = 0; i < ACH; i++) {
            int u = tid + 256*i; int r = u >> 3, c4 = u & 7;
            cp16(smbase + (s*AW + r*36 + c4*4)*4,
                 &A[(size_t)(bm + r)*K + ktc + c4*4]);
        }
        #pragma unroll
        for (int i = 0; i < 4; i++) {
            int u = tid + 256*i; int r = u >> 3, c4 = u & 7;
            cp16(smbase + (2*AW + s*BW + r*36 + c4*4)*4,
                 &Bt[(size_t)(bn + r)*K + ktc + c4*4]);
        }
    };

    issue(0, 0); CP_COMMIT;
    issue(32, 1); CP_COMMIT;
    CP_WAIT(1);
    __syncthreads();

    int nTiles = K / 32;   // 16
    for (int t = 0; t < nTiles; t++) {
        int s = t & 1;
        const uint32_t* As = smg + s*AW;
        const uint32_t* Bs = smg + 2*AW + s*BW;

        #pragma unroll
        for (int h = 0; h < 2; h++) {
            uint32_t Ar[2][2][4];
            #pragma unroll
            for (int im = 0; im < 2; im++) {
                int r0 = wm*32 + im*16 + g;
                *(uint4*)Ar[im][0] = *(const uint4*)&As[r0*36 + 8*tig + 4*h];
                *(uint4*)Ar[im][1] = *(const uint4*)&As[(r0+8)*36 + 8*tig + 4*h];
            }
            uint32_t Br[NT][4];
            #pragma unroll
            for (int nt = 0; nt < NT; nt++)
                *(uint4*)Br[nt] = *(const uint4*)&Bs[(wn*(NT*8) + nt*8 + g)*36 + 8*tig + 4*h];
            #pragma unroll
            for (int im = 0; im < 2; im++)
                #pragma unroll
                for (int nt = 0; nt < NT; nt++) {
                    MMA_TF32(acc[im][nt], Ar[im][0][0], Ar[im][1][0],
                             Ar[im][0][1], Ar[im][1][1], Br[nt][0], Br[nt][1]);
                    MMA_TF32(acc[im][nt], Ar[im][0][2], Ar[im][1][2],
                             Ar[im][0][3], Ar[im][1][3], Br[nt][2], Br[nt][3]);
                }
        }

        if (t + 1 < nTiles) {
            __syncthreads();   // all warps done reading stage s
            if (t + 2 < nTiles) { issue((t+2)*32, s); CP_COMMIT; CP_WAIT(1); }
            else                { CP_WAIT(0); }
            __syncthreads();   // stage s^1 data visible
        }
    }

    #pragma unroll
    for (int nt = 0; nt < NT; nt++) {
        int col = bn + wn*(NT*8) + nt*8 + tig*2;
        float b0 = 0.f, b1 = 0.f;
        if (bias) { b0 = bias[col]; b1 = bias[col+1]; }
        #pragma unroll
        for (int im = 0; im < 2; im++) {
            int row = bm + wm*32 + im*16 + g;
            float c0 = acc[im][nt][0] + b0, c1 = acc[im][nt][1] + b1;
            float c2 = acc[im][nt][2] + b0, c3 = acc[im][nt][3] + b1;
            if (ROUND) { c0 = rnd_tf32(c0); c1 = rnd_tf32(c1);
                         c2 = rnd_tf32(c2); c3 = rnd_tf32(c3); }
            *(float2*)&C[(size_t)row * N + col] = make_float2(c0, c1);
            *(float2*)&C[(size_t)(row + 8) * N + col] = make_float2(c2, c3);
        }
    }
}

// ---------------------------------------------------------------------------
// Attention. Block = (64-query tile, head, batch). tf32 mma throughout.
// Q[64][68], K[160][68] natural [j][d]; V[160][72]; P aliased over Q+K, stride 164.
// Score phase uses LDS.128 fragment loads (k-run mapping); PV as R3.
// ---------------------------------------------------------------------------
#define AT_QS 68
#define AT_KS 68
#define AT_VS 72
#define AT_SS 164

#define AOFF_V   0
#define AOFF_RED (AOFF_V + 160*AT_VS)        // 11520, 384 words
#define R_ML 0
#define R_MG 128
#define R_SL 192
#define R_SG 320
#define AOFF_Q   (AOFF_RED + 384)            // 11904
#define AOFF_K   (AOFF_Q + 64*AT_QS)         // 16256
#define AOFF_S   AOFF_Q                      // alias: 64*164=10496 <= 15232
#define ATT_WORDS (AOFF_K + 160*AT_KS)       // 27136 words = 108544 B

__global__ __launch_bounds__(256, 2) void attn_kernel() {
    extern __shared__ uint32_t sm[];
    float* smf = (float*)sm;
    uint32_t smbase = (uint32_t)__cvta_generic_to_shared(sm);

    const float* qkv = g_qkv;
    int qb = blockIdx.x, h = blockIdx.y, b = blockIdx.z;
    int tid = threadIdx.x;
    int warp = tid >> 5, lane = tid & 31;
    int g = lane >> 2, tig = lane & 3;
    int wm = warp & 3, wn = warp >> 2;
    int qstart = qb * 64;
    const float NEG = -1e30f;

    // ---- tile loads via cp.async (qkv already tf32-rounded) ----
    for (int u = tid; u < 6144; u += 256) {
        uint32_t dst; const float* src;
        if (u < 1024) {
            int r = u >> 4, c4 = u & 15;
            dst = AOFF_Q + r*AT_QS + c4*4;
            src = &qkv[((size_t)(b*NN + qstart + r))*QKVC + h*DH + c4*4];
        } else if (u < 3584) {
            int v = u - 1024; int r = v >> 4, c4 = v & 15;
            int kidx = (r < 128) ? max(qstart - 64 + r, 0) : (r - 128)*WIN;
            dst = AOFF_K + r*AT_KS + c4*4;
            src = &qkv[((size_t)(b*NN + kidx))*QKVC + h*DH + CC + c4*4];
        } else {
            int v = u - 3584; int r = v >> 4, c4 = v & 15;
            int kidx = (r < 128) ? max(qstart - 64 + r, 0) : (r - 128)*WIN;
            dst = AOFF_V + r*AT_VS + c4*4;
            src = &qkv[((size_t)(b*NN + kidx))*QKVC + h*DH + 2*CC + c4*4];
        }
        cp16(smbase + dst*4, src);
    }
    CP_COMMIT; CP_WAIT(0);
    __syncthreads();

    // ---- score mma: warp tile 16m x 80n, k=64, LDS.128 frags ----
    float acc[10][4];
    #pragma unroll
    for (int n = 0; n < 10; n++)
        #pragma unroll
        for (int c = 0; c < 4; c++) acc[n][c] = 0.f;

    int row0 = wm*16 + g, row1 = row0 + 8;
    #pragma unroll
    for (int ch = 0; ch < 2; ch++)
        #pragma unroll
        for (int hh = 0; hh < 2; hh++) {
            uint32_t Ar0[4], Ar1[4];
            *(uint4*)Ar0 = *(const uint4*)&sm[AOFF_Q + row0*AT_QS + ch*32 + 8*tig + 4*hh];
            *(uint4*)Ar1 = *(const uint4*)&sm[AOFF_Q + row1*AT_QS + ch*32 + 8*tig + 4*hh];
            uint32_t Br[10][4];
            #pragma unroll
            for (int nt = 0; nt < 10; nt++)
                *(uint4*)Br[nt] = *(const uint4*)&sm[AOFF_K + (wn*80 + nt*8 + g)*AT_KS
                                                     + ch*32 + 8*tig + 4*hh];
            #pragma unroll
            for (int nt = 0; nt < 10; nt++) {
                MMA_TF32(acc[nt], Ar0[0], Ar1[0], Ar0[1], Ar1[1], Br[nt][0], Br[nt][1]);
                MMA_TF32(acc[nt], Ar0[2], Ar1[2], Ar0[3], Ar1[3], Br[nt][2], Br[nt][3]);
            }
        }

    // ---- mask + scale ----
    int minj = 64 - qstart;
    #pragma unroll
    for (int n = 0; n < 10; n++) {
        int cb = wn*80 + n*8;
        int c0 = cb + tig*2, c1 = c0 + 1;
        if (cb < 128) {
            bool v00 = (c0 >= row0) && (c0 <= row0 + 64) && (c0 >= minj);
            bool v01 = (c1 >= row0) && (c1 <= row0 + 64) && (c1 >= minj);
            bool v10 = (c0 >= row1) && (c0 <= row1 + 64) && (c0 >= minj);
            bool v11 = (c1 >= row1) && (c1 <= row1 + 64) && (c1 >= minj);
            acc[n][0] = v00 ? acc[n][0]*0.125f : NEG;
            acc[n][1] = v01 ? acc[n][1]*0.125f : NEG;
            acc[n][2] = v10 ? acc[n][2]*0.125f : NEG;
            acc[n][3] = v11 ? acc[n][3]*0.125f : NEG;
        } else {
            acc[n][0] *= 0.125f; acc[n][1] *= 0.125f;
            acc[n][2] *= 0.125f; acc[n][3] *= 0.125f;
        }
    }

    // ---- softmax: register partials + quad shuffles + smem combine ----
    int nLoc = (wn == 0) ? 10 : 6;
    float m0 = NEG, m1 = NEG;
    for (int n = 0; n < nLoc; n++) {
        m0 = fmaxf(m0, fmaxf(acc[n][0], acc[n][1]));
        m1 = fmaxf(m1, fmaxf(acc[n][2], acc[n][3]));
    }
    m0 = fmaxf(m0, __shfl_xor_sync(0xffffffffu, m0, 1));
    m0 = fmaxf(m0, __shfl_xor_sync(0xffffffffu, m0, 2));
    m1 = fmaxf(m1, __shfl_xor_sync(0xffffffffu, m1, 1));
    m1 = fmaxf(m1, __shfl_xor_sync(0xffffffffu, m1, 2));
    float mg0 = NEG, mg1 = NEG;
    if (wn == 1) {
        for (int n = 6; n < 10; n++) {
            mg0 = fmaxf(mg0, fmaxf(acc[n][0], acc[n][1]));
            mg1 = fmaxf(mg1, fmaxf(acc[n][2], acc[n][3]));
        }
        mg0 = fmaxf(mg0, __shfl_xor_sync(0xffffffffu, mg0, 1));
        mg0 = fmaxf(mg0, __shfl_xor_sync(0xffffffffu, mg0, 2));
        mg1 = fmaxf(mg1, __shfl_xor_sync(0xffffffffu, mg1, 1));
        mg1 = fmaxf(mg1, __shfl_xor_sync(0xffffffffu, mg1, 2));
    }
    if (tig == 0) {
        smf[AOFF_RED + R_ML + wn*64 + row0] = m0;
        smf[AOFF_RED + R_ML + wn*64 + row1] = m1;
        if (wn == 1) {
            smf[AOFF_RED + R_MG + row0] = mg0;
            smf[AOFF_RED + R_MG + row1] = mg1;
        }
    }
    __syncthreads();

    float mL0 = fmaxf(smf[AOFF_RED + R_ML + row0], smf[AOFF_RED + R_ML + 64 + row0]);
    float mL1 = fmaxf(smf[AOFF_RED + R_ML + row1], smf[AOFF_RED + R_ML + 64 + row1]);
    float mG0 = smf[AOFF_RED + R_MG + row0];
    float mG1 = smf[AOFF_RED + R_MG + row1];

    float s0 = 0.f, s1 = 0.f, sg0 = 0.f, sg1 = 0.f;
    for (int n = 0; n < nLoc; n++) {
        acc[n][0] = __expf(acc[n][0] - mL0); s0 += acc[n][0];
        acc[n][1] = __expf(acc[n][1] - mL0); s0 += acc[n][1];
        acc[n][2] = __expf(acc[n][2] - mL1); s1 += acc[n][2];
        acc[n][3] = __expf(acc[n][3] - mL1); s1 += acc[n][3];
    }
    if (wn == 1) {
        for (int n = 6; n < 10; n++) {
            acc[n][0] = __expf(acc[n][0] - mG0); sg0 += acc[n][0];
            acc[n][1] = __expf(acc[n][1] - mG0); sg0 += acc[n][1];
            acc[n][2] = __expf(acc[n][2] - mG1); sg1 += acc[n][2];
            acc[n][3] = __expf(acc[n][3] - mG1); sg1 += acc[n][3];
        }
    }
    s0 += __shfl_xor_sync(0xffffffffu, s0, 1);
    s0 += __shfl_xor_sync(0xffffffffu, s0, 2);
    s1 += __shfl_xor_sync(0xffffffffu, s1, 1);
    s1 += __shfl_xor_sync(0xffffffffu, s1, 2);
    if (wn == 1) {
        sg0 += __shfl_xor_sync(0xffffffffu, sg0, 1);
        sg0 += __shfl_xor_sync(0xffffffffu, sg0, 2);
        sg1 += __shfl_xor_sync(0xffffffffu, sg1, 1);
        sg1 += __shfl_xor_sync(0xffffffffu, sg1, 2);
    }
    if (tig == 0) {
        smf[AOFF_RED + R_SL + wn*64 + row0] = s0;
        smf[AOFF_RED + R_SL + wn*64 + row1] = s1;
        if (wn == 1) {
            smf[AOFF_RED + R_SG + row0] = sg0;
            smf[AOFF_RED + R_SG + row1] = sg1;
        }
    }
    __syncthreads();   // also: all mma reads of sQ/sK complete before P overwrite

    float iL0 = 1.f / (smf[AOFF_RED + R_SL + row0] + smf[AOFF_RED + R_SL + 64 + row0]);
    float iL1 = 1.f / (smf[AOFF_RED + R_SL + row1] + smf[AOFF_RED + R_SL + 64 + row1]);
    float iG0 = 1.f / smf[AOFF_RED + R_SG + row0];
    float iG1 = 1.f / smf[AOFF_RED + R_SG + row1];

    #pragma unroll
    for (int n = 0; n < 10; n++) {
        int cb = wn*80 + n*8;
        int c0 = cb + tig*2;
        float f0, f1, f2, f3;
        if (n < nLoc || wn == 0) { f0 = acc[n][0]*iL0; f1 = acc[n][1]*iL0;
                                   f2 = acc[n][2]*iL1; f3 = acc[n][3]*iL1; }
        else                     { f0 = acc[n][0]*iG0; f1 = acc[n][1]*iG0;
                                   f2 = acc[n][2]*iG1; f3 = acc[n][3]*iG1; }
        sm[AOFF_S + row0*AT_SS + c0]     = f2tf32(f0);
        sm[AOFF_S + row0*AT_SS + c0 + 1] = f2tf32(f1);
        sm[AOFF_S + row1*AT_SS + c0]     = f2tf32(f2);
        sm[AOFF_S + row1*AT_SS + c0 + 1] = f2tf32(f3);
    }
    __syncthreads();

    // ---- PV mma: warp tile 16m x 32n, k=160 (natural mapping, R3-verified) ----
    float acc2[4][4];
    #pragma unroll
    for (int n = 0; n < 4; n++)
        #pragma unroll
        for (int c = 0; c < 4; c++) acc2[n][c] = 0.f;

    #pragma unroll
    for (int ks = 0; ks < 20; ks++) {
        int k0 = ks * 8;
        uint32_t a0 = sm[AOFF_S + row0*AT_SS + k0 + tig];
        uint32_t a1 = sm[AOFF_S + row1*AT_SS + k0 + tig];
        uint32_t a2 = sm[AOFF_S + row0*AT_SS + k0 + tig + 4];
        uint32_t a3 = sm[AOFF_S + row1*AT_SS + k0 + tig + 4];
        #pragma unroll
        for (int n = 0; n < 4; n++) {
            int cb = wn*32 + n*8;
            uint32_t b0 = sm[AOFF_V + (k0 + tig)*AT_VS + cb + g];
            uint32_t b1 = sm[AOFF_V + (k0 + tig + 4)*AT_VS + cb + g];
            MMA_TF32(acc2[n], a0, a1, a2, a3, b0, b1);
        }
    }

    // ---- output (tf32-rounded for gemm2) ----
    #pragma unroll
    for (int n = 0; n < 4; n++) {
        int col = h*DH + wn*32 + n*8 + tig*2;
        size_t r0o = ((size_t)(b*NN + qstart + row0)) * CC + col;
        size_t r1o = ((size_t)(b*NN + qstart + row1)) * CC + col;
        *(float2*)&g_att[r0o] = make_float2(rnd_tf32(acc2[n][0]), rnd_tf32(acc2[n][1]));
        *(float2*)&g_att[r1o] = make_float2(rnd_tf32(acc2[n][2]), rnd_tf32(acc2[n][3]));
    }
}

// ---------------------------------------------------------------------------
// launch
// ---------------------------------------------------------------------------
extern "C" void kernel_launch(void* const* d_in, const int* in_sizes, int n_in,
                              void* d_out, int out_size) {
    const float* x       = (const float*)d_in[0];
    const float* w_qkv   = (const float*)d_in[1];
    const float* lA_qkv  = (const float*)d_in[2];
    const float* lB_qkv  = (const float*)d_in[3];
    const float* w_out   = (const float*)d_in[4];
    const float* b_out   = (const float*)d_in[5];
    const float* lA_out  = (const float*)d_in[6];
    const float* lB_out  = (const float*)d_in[7];
    float* out = (float*)d_out;

    float *p_weff, *p_wout, *p_xr, *p_qkv, *p_att;
    cudaGetSymbolAddress((void**)&p_weff, g_weff);
    cudaGetSymbolAddress((void**)&p_wout, g_wout);
    cudaGetSymbolAddress((void**)&p_xr,   g_xr);
    cudaGetSymbolAddress((void**)&p_qkv,  g_qkv);
    cudaGetSymbolAddress((void**)&p_att,  g_att);

    // 1. prep: fold LoRA (transposed, rounded) + round x
    {
        int total = QKVC*CC + CC*CC + (MTOT*CC)/4;   // 1,572,864
        prep_kernel<<<(total + 255)/256, 256>>>(x, w_qkv, lA_qkv, lB_qkv,
                                                w_out, lA_out, lB_out);
    }
    // 2. qkv = xr @ weffT^T  (rounded output)
    {
        int smem = (2*128*36 + 2*128*36) * 4;   // 73728
        cudaFuncSetAttribute((const void*)tf32_gemm<128, true>,
                             cudaFuncAttributeMaxDynamicSharedMemorySize, smem);
        dim3 grid(QKVC/128, MTOT/128);
        tf32_gemm<128, true><<<grid, 256, smem>>>(p_xr, p_weff, nullptr, p_qkv,
                                                  MTOT, QKVC, CC);
    }
    // 3. attention
    {
        int smem = ATT_WORDS * 4;   // 108544
        cudaFuncSetAttribute((const void*)attn_kernel,
                             cudaFuncAttributeMaxDynamicSharedMemorySize, smem);
        dim3 grid(NN/64, HEADS, BB);
        attn_kernel<<<grid, 256, smem>>>();
    }
    // 4. out = att @ woutT^T + b_out
    {
        int smem = (2*64*36 + 2*128*36) * 4;    // 55296
        cudaFuncSetAttribute((const void*)tf32_gemm<64, false>,
                             cudaFuncAttributeMaxDynamicSharedMemorySize, smem);
        dim3 grid(CC/128, MTOT/64);
        tf32_gemm<64, false><<<grid, 256, smem>>>(p_att, p_wout, b_out, out,
                                                  MTOT, CC, CC);
    }
}

// round 5
// speedup vs baseline: 3.3755x; 1.0003x over previous
#include <cuda_runtime.h>
#include <cuda_bf16.h>
#include <math.h>
#include <stdint.h>

// Problem constants
#define BB   2
#define NN   2048
#define CC   512
#define HEADS 8
#define DH   64
#define WIN  64
#define RR   8
#define MTOT (BB*NN)        // 4096
#define QKVC (3*CC)         // 1536
#define LORA_SC 0.25f

// Scratch (device globals)
__device__ float g_weff[QKVC*CC];   // effective W_qkv, TRANSPOSED [n][k], tf32-rounded
__device__ float g_wout[CC*CC];     // effective W_out, TRANSPOSED [n][k], tf32-rounded
__device__ float g_qkv[MTOT*QKVC];  // gemm1 output, tf32-rounded
__device__ float g_att[MTOT*CC];    // attention output, tf32-rounded

__device__ __forceinline__ uint32_t f2tf32(float f) {
    uint32_t r;
    asm volatile("cvt.rna.tf32.f32 %0, %1;" : "=r"(r) : "f"(f));
    return r;
}
__device__ __forceinline__ float rnd_tf32(float f) { return __uint_as_float(f2tf32(f)); }
__device__ __forceinline__ uint32_t u2tf32(uint32_t u) { return f2tf32(__uint_as_float(u)); }

__device__ __forceinline__ void cp16(uint32_t saddr, const void* gptr) {
    asm volatile("cp.async.ca.shared.global [%0], [%1], 16;\n" :: "r"(saddr), "l"(gptr));
}
#define CP_COMMIT asm volatile("cp.async.commit_group;\n" ::: "memory")
#define CP_WAIT(n) asm volatile("cp.async.wait_group %0;\n" :: "n"(n) : "memory")

#define MMA_TF32(acc, a0,a1,a2,a3, b0,b1)                                     \
    asm volatile(                                                              \
        "mma.sync.aligned.m16n8k8.row.col.f32.tf32.tf32.f32 "                  \
        "{%0,%1,%2,%3}, {%4,%5,%6,%7}, {%8,%9}, {%0,%1,%2,%3};\n"              \
        : "+f"(acc[0]), "+f"(acc[1]), "+f"(acc[2]), "+f"(acc[3])               \
        : "r"(a0), "r"(a1), "r"(a2), "r"(a3), "r"(b0), "r"(b1))

// ---------------------------------------------------------------------------
// Prep: fold LoRA into transposed tf32-rounded effective weights (weights only)
// ---------------------------------------------------------------------------
__global__ void prep_kernel(const float* __restrict__ Wq,
                            const float* __restrict__ Aq,
                            const float* __restrict__ Bq,
                            const float* __restrict__ Wo,
                            const float* __restrict__ Ao,
                            const float* __restrict__ Bo) {
    int idx = blockIdx.x * blockDim.x + threadIdx.x;
    if (idx < QKVC*CC) {
        int j = idx / CC, i = idx - j*CC;      // weffT[j][i]
        float acc = Wq[i*QKVC + j];
        #pragma unroll
        for (int r = 0; r < RR; r++)
            acc += LORA_SC * Aq[i*RR + r] * Bq[r*QKVC + j];
        g_weff[idx] = rnd_tf32(acc);
    } else if (idx < QKVC*CC + CC*CC) {
        int k = idx - QKVC*CC;
        int j = k / CC, i = k - j*CC;          // woutT[j][i]
        float acc = Wo[i*CC + j];
        #pragma unroll
        for (int r = 0; r < RR; r++)
            acc += LORA_SC * Ao[i*RR + r] * Bo[r*CC + j];
        g_wout[k] = rnd_tf32(acc);
    }
}

// ---------------------------------------------------------------------------
// tf32 mma GEMM, cp.async 2-stage pipeline with ONE barrier per k-tile.
// C[M][N] = A[M][K] * Bt[N][K]^T (+bias). Bt pre-rounded tf32.
// CVTA: A is raw fp32, round fragments in-register after LDS.
// BN=128, BK=32; BM template. 256 threads = 8 warps.
// ---------------------------------------------------------------------------
template<int BM, bool ROUND, bool CVTA>
__global__ __launch_bounds__(256, 2) void tf32_gemm(
    const float* __restrict__ A, const float* __restrict__ Bt,
    const float* __restrict__ bias, float* __restrict__ C,
    int M, int N, int K) {
    constexpr int WM = BM/32;        // warps along m
    constexpr int WN = 8/WM;         // warps along n
    constexpr int NT = 128/(WN*8);   // 8-col n-tiles per warp
    constexpr int ACH = BM/32;       // A cp.async chunks per thread
    constexpr int AW = BM*36;        // words per A stage
    constexpr int BW = 128*36;       // words per B stage

    extern __shared__ uint32_t smg[];
    uint32_t smbase = (uint32_t)__cvta_generic_to_shared(smg);

    int tid = threadIdx.x;
    int warp = tid >> 5, lane = tid & 31;
    int wm = warp % WM, wn = warp / WM;
    int g = lane >> 2, tig = lane & 3;
    int bm = blockIdx.y * BM;
    int bn = blockIdx.x * 128;

    float acc[2][NT][4];
    #pragma unroll
    for (int im = 0; im < 2; im++)
        #pragma unroll
        for (int nt = 0; nt < NT; nt++)
            #pragma unroll
            for (int c = 0; c < 4; c++) acc[im][nt][c] = 0.f;

    // hoisted fragment offsets (within a stage)
    int aoff[2][2], boff[NT];
    #pragma unroll
    for (int im = 0; im < 2; im++) {
        int r0 = wm*32 + im*16 + g;
        aoff[im][0] = r0*36 + 8*tig;
        aoff[im][1] = (r0+8)*36 + 8*tig;
    }
    #pragma unroll
    for (int nt = 0; nt < NT; nt++)
        boff[nt] = (wn*(NT*8) + nt*8 + g)*36 + 8*tig;

    auto issue = [&](int ktc, int s) {
        #pragma unroll
        for (int i = 0; i < ACH; i++) {
            int u = tid + 256*i; int r = u >> 3, c4 = u & 7;
            cp16(smbase + (s*AW + r*36 + c4*4)*4,
                 &A[(size_t)(bm + r)*K + ktc + c4*4]);
        }
        #pragma unroll
        for (int i = 0; i < 4; i++) {
            int u = tid + 256*i; int r = u >> 3, c4 = u & 7;
            cp16(smbase + (2*AW + s*BW + r*36 + c4*4)*4,
                 &Bt[(size_t)(bn + r)*K + ktc + c4*4]);
        }
    };

    issue(0, 0); CP_COMMIT;
    CP_WAIT(0);
    __syncthreads();

    int nTiles = K / 32;   // 16
    for (int t = 0; t < nTiles; t++) {
        int s = t & 1;
        const uint32_t* As = smg + s*AW;
        const uint32_t* Bs = smg + 2*AW + s*BW;

        if (t + 1 < nTiles) { issue((t+1)*32, s^1); CP_COMMIT; }

        #pragma unroll
        for (int h = 0; h < 2; h++) {
            uint32_t Ar[2][2][4];
            #pragma unroll
            for (int im = 0; im < 2; im++) {
                *(uint4*)Ar[im][0] = *(const uint4*)&As[aoff[im][0] + 4*h];
                *(uint4*)Ar[im][1] = *(const uint4*)&As[aoff[im][1] + 4*h];
                if (CVTA) {
                    #pragma unroll
                    for (int q = 0; q < 4; q++) {
                        Ar[im][0][q] = u2tf32(Ar[im][0][q]);
                        Ar[im][1][q] = u2tf32(Ar[im][1][q]);
                    }
                }
            }
            uint32_t Br[NT][4];
            #pragma unroll
            for (int nt = 0; nt < NT; nt++)
                *(uint4*)Br[nt] = *(const uint4*)&Bs[boff[nt] + 4*h];
            #pragma unroll
            for (int im = 0; im < 2; im++)
                #pragma unroll
                for (int nt = 0; nt < NT; nt++) {
                    MMA_TF32(acc[im][nt], Ar[im][0][0], Ar[im][1][0],
                             Ar[im][0][1], Ar[im][1][1], Br[nt][0], Br[nt][1]);
                    MMA_TF32(acc[im][nt], Ar[im][0][2], Ar[im][1][2],
                             Ar[im][0][3], Ar[im][1][3], Br[nt][2], Br[nt][3]);
                }
        }

        if (t + 1 < nTiles) {
            CP_WAIT(0);
            __syncthreads();
        }
    }

    #pragma unroll
    for (int nt = 0; nt < NT; nt++) {
        int col = bn + wn*(NT*8) + nt*8 + tig*2;
        float b0 = 0.f, b1 = 0.f;
        if (bias) { b0 = bias[col]; b1 = bias[col+1]; }
        #pragma unroll
        for (int im = 0; im < 2; im++) {
            int row = bm + wm*32 + im*16 + g;
            float c0 = acc[im][nt][0] + b0, c1 = acc[im][nt][1] + b1;
            float c2 = acc[im][nt][2] + b0, c3 = acc[im][nt][3] + b1;
            if (ROUND) { c0 = rnd_tf32(c0); c1 = rnd_tf32(c1);
                         c2 = rnd_tf32(c2); c3 = rnd_tf32(c3); }
            *(float2*)&C[(size_t)row * N + col] = make_float2(c0, c1);
            *(float2*)&C[(size_t)(row + 8) * N + col] = make_float2(c2, c3);
        }
    }
}

// ---------------------------------------------------------------------------
// Attention (identical to R4-verified version).
// ---------------------------------------------------------------------------
#define AT_QS 68
#define AT_KS 68
#define AT_VS 72
#define AT_SS 164

#define AOFF_V   0
#define AOFF_RED (AOFF_V + 160*AT_VS)
#define R_ML 0
#define R_MG 128
#define R_SL 192
#define R_SG 320
#define AOFF_Q   (AOFF_RED + 384)
#define AOFF_K   (AOFF_Q + 64*AT_QS)
#define AOFF_S   AOFF_Q
#define ATT_WORDS (AOFF_K + 160*AT_KS)

__global__ __launch_bounds__(256, 2) void attn_kernel() {
    extern __shared__ uint32_t sm[];
    float* smf = (float*)sm;
    uint32_t smbase = (uint32_t)__cvta_generic_to_shared(sm);

    const float* qkv = g_qkv;
    int qb = blockIdx.x, h = blockIdx.y, b = blockIdx.z;
    int tid = threadIdx.x;
    int warp = tid >> 5, lane = tid & 31;
    int g = lane >> 2, tig = lane & 3;
    int wm = warp & 3, wn = warp >> 2;
    int qstart = qb * 64;
    const float NEG = -1e30f;

    for (int u = tid; u < 6144; u += 256) {
        uint32_t dst; const float* src;
        if (u < 1024) {
            int r = u >> 4, c4 = u & 15;
            dst = AOFF_Q + r*AT_QS + c4*4;
            src = &qkv[((size_t)(b*NN + qstart + r))*QKVC + h*DH + c4*4];
        } else if (u < 3584) {
            int v = u - 1024; int r = v >> 4, c4 = v & 15;
            int kidx = (r < 128) ? max(qstart - 64 + r, 0) : (r - 128)*WIN;
            dst = AOFF_K + r*AT_KS + c4*4;
            src = &qkv[((size_t)(b*NN + kidx))*QKVC + h*DH + CC + c4*4];
        } else {
            int v = u - 3584; int r = v >> 4, c4 = v & 15;
            int kidx = (r < 128) ? max(qstart - 64 + r, 0) : (r - 128)*WIN;
            dst = AOFF_V + r*AT_VS + c4*4;
            src = &qkv[((size_t)(b*NN + kidx))*QKVC + h*DH + 2*CC + c4*4];
        }
        cp16(smbase + dst*4, src);
    }
    CP_COMMIT; CP_WAIT(0);
    __syncthreads();

    float acc[10][4];
    #pragma unroll
    for (int n = 0; n < 10; n++)
        #pragma unroll
        for (int c = 0; c < 4; c++) acc[n][c] = 0.f;

    int row0 = wm*16 + g, row1 = row0 + 8;
    #pragma unroll
    for (int ch = 0; ch < 2; ch++)
        #pragma unroll
        for (int hh = 0; hh < 2; hh++) {
            uint32_t Ar0[4], Ar1[4];
            *(uint4*)Ar0 = *(const uint4*)&sm[AOFF_Q + row0*AT_QS + ch*32 + 8*tig + 4*hh];
            *(uint4*)Ar1 = *(const uint4*)&sm[AOFF_Q + row1*AT_QS + ch*32 + 8*tig + 4*hh];
            uint32_t Br[10][4];
            #pragma unroll
            for (int nt = 0; nt < 10; nt++)
                *(uint4*)Br[nt] = *(const uint4*)&sm[AOFF_K + (wn*80 + nt*8 + g)*AT_KS
                                                     + ch*32 + 8*tig + 4*hh];
            #pragma unroll
            for (int nt = 0; nt < 10; nt++) {
                MMA_TF32(acc[nt], Ar0[0], Ar1[0], Ar0[1], Ar1[1], Br[nt][0], Br[nt][1]);
                MMA_TF32(acc[nt], Ar0[2], Ar1[2], Ar0[3], Ar1[3], Br[nt][2], Br[nt][3]);
            }
        }

    int minj = 64 - qstart;
    #pragma unroll
    for (int n = 0; n < 10; n++) {
        int cb = wn*80 + n*8;
        int c0 = cb + tig*2, c1 = c0 + 1;
        if (cb < 128) {
            bool v00 = (c0 >= row0) && (c0 <= row0 + 64) && (c0 >= minj);
            bool v01 = (c1 >= row0) && (c1 <= row0 + 64) && (c1 >= minj);
            bool v10 = (c0 >= row1) && (c0 <= row1 + 64) && (c0 >= minj);
            bool v11 = (c1 >= row1) && (c1 <= row1 + 64) && (c1 >= minj);
            acc[n][0] = v00 ? acc[n][0]*0.125f : NEG;
            acc[n][1] = v01 ? acc[n][1]*0.125f : NEG;
            acc[n][2] = v10 ? acc[n][2]*0.125f : NEG;
            acc[n][3] = v11 ? acc[n][3]*0.125f : NEG;
        } else {
            acc[n][0] *= 0.125f; acc[n][1] *= 0.125f;
            acc[n][2] *= 0.125f; acc[n][3] *= 0.125f;
        }
    }

    int nLoc = (wn == 0) ? 10 : 6;
    float m0 = NEG, m1 = NEG;
    for (int n = 0; n < nLoc; n++) {
        m0 = fmaxf(m0, fmaxf(acc[n][0], acc[n][1]));
        m1 = fmaxf(m1, fmaxf(acc[n][2], acc[n][3]));
    }
    m0 = fmaxf(m0, __shfl_xor_sync(0xffffffffu, m0, 1));
    m0 = fmaxf(m0, __shfl_xor_sync(0xffffffffu, m0, 2));
    m1 = fmaxf(m1, __shfl_xor_sync(0xffffffffu, m1, 1));
    m1 = fmaxf(m1, __shfl_xor_sync(0xffffffffu, m1, 2));
    float mg0 = NEG, mg1 = NEG;
    if (wn == 1) {
        for (int n = 6; n < 10; n++) {
            mg0 = fmaxf(mg0, fmaxf(acc[n][0], acc[n][1]));
            mg1 = fmaxf(mg1, fmaxf(acc[n][2], acc[n][3]));
        }
        mg0 = fmaxf(mg0, __shfl_xor_sync(0xffffffffu, mg0, 1));
        mg0 = fmaxf(mg0, __shfl_xor_sync(0xffffffffu, mg0, 2));
        mg1 = fmaxf(mg1, __shfl_xor_sync(0xffffffffu, mg1, 1));
        mg1 = fmaxf(mg1, __shfl_xor_sync(0xffffffffu, mg1, 2));
    }
    if (tig == 0) {
        smf[AOFF_RED + R_ML + wn*64 + row0] = m0;
        smf[AOFF_RED + R_ML + wn*64 + row1] = m1;
        if (wn == 1) {
            smf[AOFF_RED + R_MG + row0] = mg0;
            smf[AOFF_RED + R_MG + row1] = mg1;
        }
    }
    __syncthreads();

    float mL0 = fmaxf(smf[AOFF_RED + R_ML + row0], smf[AOFF_RED + R_ML + 64 + row0]);
    float mL1 = fmaxf(smf[AOFF_RED + R_ML + row1], smf[AOFF_RED + R_ML + 64 + row1]);
    float mG0 = smf[AOFF_RED + R_MG + row0];
    float mG1 = smf[AOFF_RED + R_MG + row1];

    float s0 = 0.f, s1 = 0.f, sg0 = 0.f, sg1 = 0.f;
    for (int n = 0; n < nLoc; n++) {
        acc[n][0] = __expf(acc[n][0] - mL0); s0 += acc[n][0];
        acc[n][1] = __expf(acc[n][1] - mL0); s0 += acc[n][1];
        acc[n][2] = __expf(acc[n][2] - mL1); s1 += acc[n][2];
        acc[n][3] = __expf(acc[n][3] - mL1); s1 += acc[n][3];
    }
    if (wn == 1) {
        for (int n = 6; n < 10; n++) {
            acc[n][0] = __expf(acc[n][0] - mG0); sg0 += acc[n][0];
            acc[n][1] = __expf(acc[n][1] - mG0); sg0 += acc[n][1];
            acc[n][2] = __expf(acc[n][2] - mG1); sg1 += acc[n][2];
            acc[n][3] = __expf(acc[n][3] - mG1); sg1 += acc[n][3];
        }
    }
    s0 += __shfl_xor_sync(0xffffffffu, s0, 1);
    s0 += __shfl_xor_sync(0xffffffffu, s0, 2);
    s1 += __shfl_xor_sync(0xffffffffu, s1, 1);
    s1 += __shfl_xor_sync(0xffffffffu, s1, 2);
    if (wn == 1) {
        sg0 += __shfl_xor_sync(0xffffffffu, sg0, 1);
        sg0 += __shfl_xor_sync(0xffffffffu, sg0, 2);
        sg1 += __shfl_xor_sync(0xffffffffu, sg1, 1);
        sg1 += __shfl_xor_sync(0xffffffffu, sg1, 2);
    }
    if (tig == 0) {
        smf[AOFF_RED + R_SL + wn*64 + row0] = s0;
        smf[AOFF_RED + R_SL + wn*64 + row1] = s1;
        if (wn == 1) {
            smf[AOFF_RED + R_SG + row0] = sg0;
            smf[AOFF_RED + R_SG + row1] = sg1;
        }
    }
    __syncthreads();

    float iL0 = 1.f / (smf[AOFF_RED + R_SL + row0] + smf[AOFF_RED + R_SL + 64 + row0]);
    float iL1 = 1.f / (smf[AOFF_RED + R_SL + row1] + smf[AOFF_RED + R_SL + 64 + row1]);
    float iG0 = 1.f / smf[AOFF_RED + R_SG + row0];
    float iG1 = 1.f / smf[AOFF_RED + R_SG + row1];

    #pragma unroll
    for (int n = 0; n < 10; n++) {
        int cb = wn*80 + n*8;
        int c0 = cb + tig*2;
        float f0, f1, f2, f3;
        if (n < nLoc || wn == 0) { f0 = acc[n][0]*iL0; f1 = acc[n][1]*iL0;
                                   f2 = acc[n][2]*iL1; f3 = acc[n][3]*iL1; }
        else                     { f0 = acc[n][0]*iG0; f1 = acc[n][1]*iG0;
                                   f2 = acc[n][2]*iG1; f3 = acc[n][3]*iG1; }
        sm[AOFF_S + row0*AT_SS + c0]     = f2tf32(f0);
        sm[AOFF_S + row0*AT_SS + c0 + 1] = f2tf32(f1);
        sm[AOFF_S + row1*AT_SS + c0]     = f2tf32(f2);
        sm[AOFF_S + row1*AT_SS + c0 + 1] = f2tf32(f3);
    }
    __syncthreads();

    float acc2[4][4];
    #pragma unroll
    for (int n = 0; n < 4; n++)
        #pragma unroll
        for (int c = 0; c < 4; c++) acc2[n][c] = 0.f;

    #pragma unroll
    for (int ks = 0; ks < 20; ks++) {
        int k0 = ks * 8;
        uint32_t a0 = sm[AOFF_S + row0*AT_SS + k0 + tig];
        uint32_t a1 = sm[AOFF_S + row1*AT_SS + k0 + tig];
        uint32_t a2 = sm[AOFF_S + row0*AT_SS + k0 + tig + 4];
        uint32_t a3 = sm[AOFF_S + row1*AT_SS + k0 + tig + 4];
        #pragma unroll
        for (int n = 0; n < 4; n++) {
            int cb = wn*32 + n*8;
            uint32_t b0 = sm[AOFF_V + (k0 + tig)*AT_VS + cb + g];
            uint32_t b1 = sm[AOFF_V + (k0 + tig + 4)*AT_VS + cb + g];
            MMA_TF32(acc2[n], a0, a1, a2, a3, b0, b1);
        }
    }

    #pragma unroll
    for (int n = 0; n < 4; n++) {
        int col = h*DH + wn*32 + n*8 + tig*2;
        size_t r0o = ((size_t)(b*NN + qstart + row0)) * CC + col;
        size_t r1o = ((size_t)(b*NN + qstart + row1)) * CC + col;
        *(float2*)&g_att[r0o] = make_float2(rnd_tf32(acc2[n][0]), rnd_tf32(acc2[n][1]));
        *(float2*)&g_att[r1o] = make_float2(rnd_tf32(acc2[n][2]), rnd_tf32(acc2[n][3]));
    }
}

// ---------------------------------------------------------------------------
// launch
// ---------------------------------------------------------------------------
extern "C" void kernel_launch(void* const* d_in, const int* in_sizes, int n_in,
                              void* d_out, int out_size) {
    const float* x       = (const float*)d_in[0];
    const float* w_qkv   = (const float*)d_in[1];
    const float* lA_qkv  = (const float*)d_in[2];
    const float* lB_qkv  = (const float*)d_in[3];
    const float* w_out   = (const float*)d_in[4];
    const float* b_out   = (const float*)d_in[5];
    const float* lA_out  = (const float*)d_in[6];
    const float* lB_out  = (const float*)d_in[7];
    float* out = (float*)d_out;

    float *p_weff, *p_wout, *p_qkv, *p_att;
    cudaGetSymbolAddress((void**)&p_weff, g_weff);
    cudaGetSymbolAddress((void**)&p_wout, g_wout);
    cudaGetSymbolAddress((void**)&p_qkv,  g_qkv);
    cudaGetSymbolAddress((void**)&p_att,  g_att);

    // 1. prep: fold LoRA into transposed, rounded weights
    {
        int total = QKVC*CC + CC*CC;
        prep_kernel<<<(total + 255)/256, 256>>>(w_qkv, lA_qkv, lB_qkv,
                                                w_out, lA_out, lB_out);
    }
    // 2. qkv = x @ weffT^T  (A converted in-register, rounded output)
    {
        int smem = (2*128*36 + 2*128*36) * 4;   // 73728
        cudaFuncSetAttribute((const void*)tf32_gemm<128, true, true>,
                             cudaFuncAttributeMaxDynamicSharedMemorySize, smem);
        dim3 grid(QKVC/128, MTOT/128);
        tf32_gemm<128, true, true><<<grid, 256, smem>>>(x, p_weff, nullptr, p_qkv,
                                                        MTOT, QKVC, CC);
    }
    // 3. attention
    {
        int smem = ATT_WORDS * 4;   // 108544
        cudaFuncSetAttribute((const void*)attn_kernel,
                             cudaFuncAttributeMaxDynamicSharedMemorySize, smem);
        dim3 grid(NN/64, HEADS, BB);
        attn_kernel<<<grid, 256, smem>>>();
    }
    // 4. out = att @ woutT^T + b_out
    {
        int smem = (2*64*36 + 2*128*36) * 4;    // 55296
        cudaFuncSetAttribute((const void*)tf32_gemm<64, false, false>,
                             cudaFuncAttributeMaxDynamicSharedMemorySize, smem);
        dim3 grid(CC/128, MTOT/64);
        tf32_gemm<64, false, false><<<grid, 256, smem>>>(p_att, p_wout, b_out, out,
                                                         MTOT, CC, CC);
    }
}